// round 7
// baseline (speedup 1.0000x reference)
#include <cuda_runtime.h>
#include <cuda_bf16.h>
#include <cuda_fp16.h>

#define NB 8
#define NT 256   // T_en == T_de
#define ND 256
#define NU 256

// Scratch (device globals: no allocation allowed in kernel_launch)
__device__ __half d_aeT_h[NB * NU * NT];  // aeT[b][u][e] fp16 (e contiguous)
__device__ float  d_ad   [NB * NT * NU];  // ad [b][t][u] fp32
__device__ __half d_en_h [NB * NT * ND];  // en[b][e][d] fp16 (d contiguous)

// ---------------------------------------------------------------------------
// Fused GEMM: att_en (fp16 transposed store) and att_de (fp32).
// ---------------------------------------------------------------------------
__global__ __launch_bounds__(256) void gemm_kernel(const float* __restrict__ en,
                                                   const float* __restrict__ de,
                                                   const float* __restrict__ w_en,
                                                   const float* __restrict__ w_de)
{
    const int z     = blockIdx.z;
    const int b     = z >> 1;
    const int which = z & 1;

    const float* A  = which ? (de + b * NT * ND) : (en + b * NT * ND);
    const float* Bm = which ? w_de : w_en;

    const int m0 = blockIdx.y * 64;
    const int n0 = blockIdx.x * 64;

    __shared__ float As[16][68];
    __shared__ float Bs[16][64];

    const int tid   = threadIdx.x;
    const int a_row = tid >> 2;
    const int a_k4  = (tid & 3) << 2;
    const int b_k   = tid >> 4;
    const int b_n4  = (tid & 15) << 2;
    const int tm    = tid >> 4;
    const int tn    = tid & 15;

    const bool emit_en = (which == 0) && (n0 == 0);

    float acc[4][4];
#pragma unroll
    for (int i = 0; i < 4; i++)
#pragma unroll
        for (int j = 0; j < 4; j++) acc[i][j] = 0.f;

    for (int k0 = 0; k0 < 256; k0 += 16) {
        float4 av = *(const float4*)(A  + (m0 + a_row) * 256 + k0 + a_k4);
        float4 bv = *(const float4*)(Bm + (k0 + b_k)   * 256 + n0 + b_n4);
        if (emit_en) {
            __half2 lo = __floats2half2_rn(av.x, av.y);
            __half2 hi = __floats2half2_rn(av.z, av.w);
            uint2 o;
            o.x = *(unsigned*)&lo;
            o.y = *(unsigned*)&hi;
            *(uint2*)(d_en_h + b * NT * ND + (m0 + a_row) * ND + k0 + a_k4) = o;
        }
        __syncthreads();
        As[a_k4 + 0][a_row] = av.x;
        As[a_k4 + 1][a_row] = av.y;
        As[a_k4 + 2][a_row] = av.z;
        As[a_k4 + 3][a_row] = av.w;
        *(float4*)&Bs[b_k][b_n4] = bv;
        __syncthreads();
#pragma unroll
        for (int k = 0; k < 16; k++) {
            float4 a4 = *(const float4*)&As[k][tm << 2];
            float4 b4 = *(const float4*)&Bs[k][tn << 2];
            float ar[4] = {a4.x, a4.y, a4.z, a4.w};
            float br[4] = {b4.x, b4.y, b4.z, b4.w};
#pragma unroll
            for (int i = 0; i < 4; i++)
#pragma unroll
                for (int j = 0; j < 4; j++)
                    acc[i][j] = fmaf(ar[i], br[j], acc[i][j]);
        }
    }

    if (which == 0) {
        __half* dst = d_aeT_h + b * NU * NT;
#pragma unroll
        for (int j = 0; j < 4; j++) {
            int u = n0 + (tn << 2) + j;
            __half2 lo = __floats2half2_rn(acc[0][j], acc[1][j]);
            __half2 hi = __floats2half2_rn(acc[2][j], acc[3][j]);
            uint2 v;
            v.x = *(unsigned*)&lo;
            v.y = *(unsigned*)&hi;
            *(uint2*)(dst + u * NT + m0 + (tm << 2)) = v;
        }
    } else {
        float* dst = d_ad + b * NT * NU;
#pragma unroll
        for (int i = 0; i < 4; i++) {
            int t = m0 + (tm << 2) + i;
            float4 v = make_float4(acc[i][0], acc[i][1], acc[i][2], acc[i][3]);
            *(float4*)(dst + t * NU + n0 + (tn << 2)) = v;
        }
    }
}

// ---------------------------------------------------------------------------
// Fused tanh-score + softmax + context. One CTA = (b, 4 decoder rows),
// 256 threads = 8 warps. Each warp owns a private 2x2KB cp.async double
// buffer and stages its own 32x32 tiles: NO CTA barriers in the mainloops.
// Warp w covers e (and d) slice [32w, 32w+32), so thread's e == tid.
// ---------------------------------------------------------------------------
#define UT 32                          // u (or e) rows per staged tile
#define NTILES 8                       // 256 / 32
#define TILE_H (UT * 32)               // halfs per warp tile (32 rows x 32 cols)

// Stage one 2KB warp tile: 32 rows x 64B. Lane l copies row l (4 x 16B).
__device__ __forceinline__ void stage_warp(unsigned sdst, const __half* gsrc_row0,
                                           int lane)
{
    unsigned s = sdst + lane * 64;
    const char* g = (const char*)gsrc_row0 + lane * 512;   // row stride 512B
    asm volatile("cp.async.cg.shared.global [%0], [%1], 16;\n"
                 "cp.async.cg.shared.global [%2], [%3], 16;\n"
                 "cp.async.cg.shared.global [%4], [%5], 16;\n"
                 "cp.async.cg.shared.global [%6], [%7], 16;\n"
                 "cp.async.commit_group;\n"
                 :: "r"(s),      "l"(g),
                    "r"(s + 16), "l"(g + 16),
                    "r"(s + 32), "l"(g + 32),
                    "r"(s + 48), "l"(g + 48) : "memory");
}

__global__ __launch_bounds__(256) void attn_kernel(const float* __restrict__ de,
                                                   const float* __restrict__ nu,
                                                   float* __restrict__ out)
{
    const int b    = blockIdx.x >> 6;          // 8 b * 64 groups
    const int t0   = (blockIdx.x & 63) << 2;   // 4 decoder rows per CTA
    const int tid  = threadIdx.x;
    const int w    = tid >> 5;
    const int lane = tid & 31;

    __shared__ __half buf[8][2][TILE_H];   // per-warp double buffers (32KB)
    __shared__ uint4  pk[256];             // {ad01, ad23, nu2, pad} per u
    __shared__ uint2  alpha_h[256];        // {half2(a0,a1), half2(a2,a3)} per e
    __shared__ float4 redM[8];
    __shared__ float4 redS[8];

    const unsigned sb[2] = {
        (unsigned)__cvta_generic_to_shared(&buf[w][0][0]),
        (unsigned)__cvta_generic_to_shared(&buf[w][1][0])
    };

    // warp's e/d slice base (halfs): column offset 32w within 256-wide rows
    const __half* aeg = d_aeT_h + b * NU * NT + w * 32;
    const __half* eng = d_en_h  + b * NT * ND + w * 32;

    // prologue: stage ae tile 0; fill pk meanwhile; one-time barrier
    stage_warp(sb[0], aeg, lane);
    {
        const float* ap = d_ad + (b * NT + t0) * NU + tid;
        __half2 ad01 = __floats2half2_rn(ap[0],      ap[NU]);
        __half2 ad23 = __floats2half2_rn(ap[2 * NU], ap[3 * NU]);
        __half2 nu2  = __float2half2_rn(nu[tid]);
        uint4 p;
        p.x = *(unsigned*)&ad01;
        p.y = *(unsigned*)&ad23;
        p.z = *(unsigned*)&nu2;
        p.w = 0;
        pk[tid] = p;
    }
    __syncthreads();

    // ---- scores: loop 256 u in 8 warp-private staged tiles (no barriers) ----
    float m0 = 0.f, m1 = 0.f, m2 = 0.f, m3 = 0.f;
    for (int t = 0; t < NTILES; ++t) {
        if (t < NTILES - 1) {
            stage_warp(sb[(t + 1) & 1], aeg + (t + 1) * UT * 256, lane);
            asm volatile("cp.async.wait_group 1;" ::: "memory");
        } else {
            asm volatile("cp.async.wait_group 0;" ::: "memory");
        }
        __syncwarp();                       // join lanes' completed copies

        const __half* sa = &buf[w][t & 1][lane];
        const int u0 = t * UT;
#pragma unroll
        for (int c = 0; c < UT; c += 16) {  // fp16 acc flushed every 16 u
            __half2 a01 = __float2half2_rn(0.f);
            __half2 a23 = __float2half2_rn(0.f);
#pragma unroll
            for (int k = 0; k < 16; k++) {
                __half  a  = sa[(c + k) << 5];     // LDS.16, conflict-free
                uint4   p  = pk[u0 + c + k];       // LDS.128 broadcast
                __half2 ah = __half2half2(a);
                __half2 c01 = __hadd2(ah, *(__half2*)&p.x);
                __half2 c23 = __hadd2(ah, *(__half2*)&p.y);
                unsigned t01, t23;
                asm("tanh.approx.f16x2 %0, %1;" : "=r"(t01) : "r"(*(unsigned*)&c01));
                asm("tanh.approx.f16x2 %0, %1;" : "=r"(t23) : "r"(*(unsigned*)&c23));
                a01 = __hfma2(*(__half2*)&t01, *(__half2*)&p.z, a01);
                a23 = __hfma2(*(__half2*)&t23, *(__half2*)&p.z, a23);
            }
            float2 f01 = __half22float2(a01);
            float2 f23 = __half22float2(a23);
            m0 += f01.x; m1 += f01.y; m2 += f23.x; m3 += f23.y;
        }
        __syncwarp();
    }

    // prefetch en tile 0 (warp-private buffer is free) — hides under softmax
    stage_warp(sb[0], eng, lane);

    // ---- softmax over e (e == tid), all 4 rows batched ----
    float4 mu = make_float4(m0, m1, m2, m3);
    float4 mx = mu;
#pragma unroll
    for (int o = 16; o; o >>= 1) {
        mx.x = fmaxf(mx.x, __shfl_xor_sync(0xffffffffu, mx.x, o));
        mx.y = fmaxf(mx.y, __shfl_xor_sync(0xffffffffu, mx.y, o));
        mx.z = fmaxf(mx.z, __shfl_xor_sync(0xffffffffu, mx.z, o));
        mx.w = fmaxf(mx.w, __shfl_xor_sync(0xffffffffu, mx.w, o));
    }
    if (lane == 0) redM[w] = mx;
    __syncthreads();
    mx = redM[0];
#pragma unroll
    for (int i = 1; i < 8; i++) {
        float4 r = redM[i];
        mx.x = fmaxf(mx.x, r.x); mx.y = fmaxf(mx.y, r.y);
        mx.z = fmaxf(mx.z, r.z); mx.w = fmaxf(mx.w, r.w);
    }
    float4 ex = make_float4(__expf(mu.x - mx.x), __expf(mu.y - mx.y),
                            __expf(mu.z - mx.z), __expf(mu.w - mx.w));
    float4 s = ex;
#pragma unroll
    for (int o = 16; o; o >>= 1) {
        s.x += __shfl_xor_sync(0xffffffffu, s.x, o);
        s.y += __shfl_xor_sync(0xffffffffu, s.y, o);
        s.z += __shfl_xor_sync(0xffffffffu, s.z, o);
        s.w += __shfl_xor_sync(0xffffffffu, s.w, o);
    }
    if (lane == 0) redS[w] = s;
    __syncthreads();
    s = redS[0];
#pragma unroll
    for (int i = 1; i < 8; i++) {
        float4 r = redS[i];
        s.x += r.x; s.y += r.y; s.z += r.z; s.w += r.w;
    }
    {
        __half2 al01 = __floats2half2_rn(__fdividef(ex.x, s.x), __fdividef(ex.y, s.y));
        __half2 al23 = __floats2half2_rn(__fdividef(ex.z, s.z), __fdividef(ex.w, s.w));
        uint2 av;
        av.x = *(unsigned*)&al01;
        av.y = *(unsigned*)&al23;
        alpha_h[tid] = av;
    }
    __syncthreads();

    // ---- context: loop 256 e in 8 warp-private staged tiles (no barriers) ----
    const float* dep = de + (b * NT + t0) * ND + tid;
    float o0 = dep[0], o1 = dep[ND], o2 = dep[2 * ND], o3 = dep[3 * ND];
    for (int t = 0; t < NTILES; ++t) {
        if (t < NTILES - 1) {
            stage_warp(sb[(t + 1) & 1], eng + (t + 1) * UT * 256, lane);
            asm volatile("cp.async.wait_group 1;" ::: "memory");
        } else {
            asm volatile("cp.async.wait_group 0;" ::: "memory");
        }
        __syncwarp();

        const __half* sv = &buf[w][t & 1][lane];
        const int e0 = t * UT;
        __half2 acc01 = __float2half2_rn(0.f);
        __half2 acc23 = __float2half2_rn(0.f);
#pragma unroll
        for (int k = 0; k < UT; k++) {
            __half2 v2 = __half2half2(sv[k << 5]);   // LDS.16
            uint2   a  = alpha_h[e0 + k];            // LDS.64 broadcast
            acc01 = __hfma2(*(__half2*)&a.x, v2, acc01);
            acc23 = __hfma2(*(__half2*)&a.y, v2, acc23);
        }
        float2 f01 = __half22float2(acc01);
        float2 f23 = __half22float2(acc23);
        o0 += f01.x; o1 += f01.y; o2 += f23.x; o3 += f23.y;
        __syncwarp();
    }
    float* op = out + (b * NT + t0) * ND + tid;
    op[0] = o0; op[ND] = o1; op[2 * ND] = o2; op[3 * ND] = o3;
}

extern "C" void kernel_launch(void* const* d_in, const int* in_sizes, int n_in,
                              void* d_out, int out_size)
{
    const float* en   = (const float*)d_in[0];   // (8,256,256)
    const float* de   = (const float*)d_in[1];   // (8,256,256)
    const float* w_en = (const float*)d_in[2];   // (256,256)
    const float* w_de = (const float*)d_in[3];   // (256,256)
    const float* nu   = (const float*)d_in[4];   // (256,1)
    float* out = (float*)d_out;                  // (8,256,256) fp32

    dim3 gg(4, 4, 16);
    gemm_kernel<<<gg, 256>>>(en, de, w_en, w_de);
    attn_kernel<<<NB * (NT / 4), 256>>>(de, nu, out);
}

// round 8
// speedup vs baseline: 1.3858x; 1.3858x over previous
#include <cuda_runtime.h>
#include <cuda_bf16.h>
#include <cuda_fp16.h>

#define NB 8
#define NT 256   // T_en == T_de
#define ND 256
#define NU 256

// Scratch (device globals: no allocation allowed in kernel_launch)
__device__ __half d_aeT_h[NB * NU * NT];  // aeT[b][u][e] fp16 (e contiguous)
__device__ float  d_ad   [NB * NT * NU];  // ad [b][t][u] fp32
__device__ __half d_en_h [NB * NT * ND];  // en[b][e][d] fp16 (d contiguous)

// ---------------------------------------------------------------------------
// tf32 tensor-core GEMM (mma.sync.m16n8k8).
//   which=0: C[e][u] = sum_d en[b][e][d] * w_en[d][u] -> d_aeT_h[b][u][e] fp16
//            (n0==0 CTAs also emit en as fp16 to d_en_h from the SMEM A tile)
//   which=1: C[t][u] = sum_d de[b][t][d] * w_de[d][u] -> d_ad[b][t][u] fp32
// CTA tile 128(M)x64(N), 8 warps of 32x32, K-chunk 32, register prefetch.
// ---------------------------------------------------------------------------
__device__ __forceinline__ unsigned f2tf(float x)
{
    unsigned r;
    asm("cvt.rna.tf32.f32 %0, %1;" : "=r"(r) : "f"(x));
    return r;
}

__device__ __forceinline__ void mma_tf32(float c[4], const unsigned a[4],
                                         unsigned b0, unsigned b1)
{
    asm volatile(
        "mma.sync.aligned.m16n8k8.row.col.f32.tf32.tf32.f32 "
        "{%0,%1,%2,%3}, {%4,%5,%6,%7}, {%8,%9}, {%0,%1,%2,%3};"
        : "+f"(c[0]), "+f"(c[1]), "+f"(c[2]), "+f"(c[3])
        : "r"(a[0]), "r"(a[1]), "r"(a[2]), "r"(a[3]), "r"(b0), "r"(b1));
}

__global__ __launch_bounds__(256) void gemm_kernel(const float* __restrict__ en,
                                                   const float* __restrict__ de,
                                                   const float* __restrict__ w_en,
                                                   const float* __restrict__ w_de)
{
    const int z     = blockIdx.z;
    const int b     = z >> 1;
    const int which = z & 1;

    const float* A  = which ? (de + b * NT * ND) : (en + b * NT * ND);  // (256,256)
    const float* Bm = which ? w_de : w_en;                               // (256,256)

    const int m0 = blockIdx.y * 128;
    const int n0 = blockIdx.x * 64;

    __shared__ float As[128][36];   // pad 36: A-frag banks (4g+tig) distinct
    __shared__ float Bs[32][68];    // pad 68: B-frag banks (4tig+g) distinct

    const int tid  = threadIdx.x;
    const int w    = tid >> 5;
    const int lane = tid & 31;
    const int g    = lane >> 2;     // group id (0..7)
    const int tig  = lane & 3;      // thread in group
    const int mw   = (w & 3) * 32;  // warp M offset
    const int nw   = (w >> 2) * 32; // warp N offset

    const bool emit_en = (which == 0) && (n0 == 0);

    float c[2][4][4];
#pragma unroll
    for (int mt = 0; mt < 2; mt++)
#pragma unroll
        for (int nt = 0; nt < 4; nt++)
#pragma unroll
            for (int i = 0; i < 4; i++) c[mt][nt][i] = 0.f;

    // prefetch registers: A 4 x float4, B 2 x float4
    float4 pa[4], pb[2];
    const int ar[4] = {tid >> 3, (tid + 256) >> 3, (tid + 512) >> 3, (tid + 768) >> 3};
    const int ac    = (tid & 7) << 2;
    const int br[2] = {tid >> 4, (tid + 256) >> 4};
    const int bc    = (tid & 15) << 2;

#pragma unroll
    for (int i = 0; i < 4; i++)
        pa[i] = *(const float4*)(A + (m0 + ar[i]) * 256 + 0 + ac);
#pragma unroll
    for (int i = 0; i < 2; i++)
        pb[i] = *(const float4*)(Bm + (0 + br[i]) * 256 + n0 + bc);

    for (int t = 0; t < 8; ++t) {
        __syncthreads();
#pragma unroll
        for (int i = 0; i < 4; i++)
            *(float4*)&As[ar[i]][ac] = pa[i];
#pragma unroll
        for (int i = 0; i < 2; i++)
            *(float4*)&Bs[br[i]][bc] = pb[i];
        __syncthreads();

        if (emit_en) {
            // publish this A tile (en) as fp16: rows m0..m0+127, cols t*32..+32
            __half* dst = d_en_h + b * NT * ND;
#pragma unroll
            for (int i = 0; i < 8; i++) {
                int q  = tid + i * 256;          // 2048 half2 per tile
                int r  = q >> 4;
                int c2 = (q & 15) << 1;
                __half2 h = __floats2half2_rn(As[r][c2], As[r][c2 + 1]);
                *(unsigned*)(dst + (m0 + r) * ND + t * 32 + c2) = *(unsigned*)&h;
            }
        }

        if (t < 7) {
            int k0 = (t + 1) * 32;
#pragma unroll
            for (int i = 0; i < 4; i++)
                pa[i] = *(const float4*)(A + (m0 + ar[i]) * 256 + k0 + ac);
#pragma unroll
            for (int i = 0; i < 2; i++)
                pb[i] = *(const float4*)(Bm + (k0 + br[i]) * 256 + n0 + bc);
        }

#pragma unroll
        for (int kt = 0; kt < 4; kt++) {
            unsigned a[2][4];
#pragma unroll
            for (int mt = 0; mt < 2; mt++) {
                int r = mw + mt * 16 + g;
                a[mt][0] = f2tf(As[r][kt * 8 + tig]);
                a[mt][1] = f2tf(As[r + 8][kt * 8 + tig]);
                a[mt][2] = f2tf(As[r][kt * 8 + tig + 4]);
                a[mt][3] = f2tf(As[r + 8][kt * 8 + tig + 4]);
            }
#pragma unroll
            for (int nt = 0; nt < 4; nt++) {
                unsigned b0 = f2tf(Bs[kt * 8 + tig][nw + nt * 8 + g]);
                unsigned b1 = f2tf(Bs[kt * 8 + tig + 4][nw + nt * 8 + g]);
                mma_tf32(c[0][nt], a[0], b0, b1);
                mma_tf32(c[1][nt], a[1], b0, b1);
            }
        }
    }

    if (which == 0) {
        // C[e][u] -> aeT_h[b][u][e] fp16 (transposed scatter, tiny volume)
        __half* dst = d_aeT_h + b * NU * NT;
#pragma unroll
        for (int mt = 0; mt < 2; mt++)
#pragma unroll
            for (int nt = 0; nt < 4; nt++) {
                int e0 = m0 + mw + mt * 16 + g;
                int u0 = n0 + nw + nt * 8 + 2 * tig;
                dst[u0 * NT + e0]           = __float2half(c[mt][nt][0]);
                dst[(u0 + 1) * NT + e0]     = __float2half(c[mt][nt][1]);
                dst[u0 * NT + e0 + 8]       = __float2half(c[mt][nt][2]);
                dst[(u0 + 1) * NT + e0 + 8] = __float2half(c[mt][nt][3]);
            }
    } else {
        float* dst = d_ad + b * NT * NU;
#pragma unroll
        for (int mt = 0; mt < 2; mt++)
#pragma unroll
            for (int nt = 0; nt < 4; nt++) {
                int row = m0 + mw + mt * 16 + g;
                int col = n0 + nw + nt * 8 + 2 * tig;
                *(float2*)(dst + row * NU + col)       = make_float2(c[mt][nt][0], c[mt][nt][1]);
                *(float2*)(dst + (row + 8) * NU + col) = make_float2(c[mt][nt][2], c[mt][nt][3]);
            }
    }
}

// ---------------------------------------------------------------------------
// Fused tanh-score + softmax + context — R4 configuration VERBATIM (best:
// 52.4us, at the MUFU tanh roofline). One CTA = (b, 4 decoder rows),
// CTA-wide 16KB cp.async double-buffered tiles.
// ---------------------------------------------------------------------------
#define UT 32                       // u (or e) values per tile
#define TILE_HALFS (UT * 256)       // 8192 halfs = 16KB
#define NTILES (256 / UT)           // 8

__device__ __forceinline__ void stage_tile(unsigned sbase, const __half* g, int tid)
{
    unsigned s = sbase + tid * 16;
    const char* gp = (const char*)g + tid * 16;
#pragma unroll
    for (int i = 0; i < 4; i++)
        asm volatile("cp.async.cg.shared.global [%0], [%1], 16;\n"
                     :: "r"(s + i * 4096), "l"(gp + i * 4096) : "memory");
    asm volatile("cp.async.commit_group;" ::: "memory");
}

__global__ __launch_bounds__(256) void attn_kernel(const float* __restrict__ de,
                                                   const float* __restrict__ nu,
                                                   float* __restrict__ out)
{
    const int b   = blockIdx.x >> 6;          // 8 b * 64 groups
    const int t0  = (blockIdx.x & 63) << 2;   // 4 decoder rows per CTA
    const int tid = threadIdx.x;

    __shared__ __half buf[2][TILE_HALFS];     // 32KB double buffer
    __shared__ uint4  pk[256];                // {ad01, ad23, nu2, pad} per u
    __shared__ float4 alpha4[256];
    __shared__ float  red[8];

    const unsigned sb0 = (unsigned)__cvta_generic_to_shared(&buf[0][0]);
    const unsigned sb1 = (unsigned)__cvta_generic_to_shared(&buf[1][0]);
    const unsigned sbb[2] = {sb0, sb1};

    const __half* aeg = d_aeT_h + b * NU * NT;   // [u][e] tiles, contiguous
    const __half* eng = d_en_h  + b * NT * ND;   // [e][d] tiles, contiguous

    // prologue: stage ae tile 0; fill pk meanwhile
    stage_tile(sb0, aeg, tid);
    {
        const float* ap = d_ad + (b * NT + t0) * NU + tid;
        __half2 ad01 = __floats2half2_rn(ap[0],      ap[NU]);
        __half2 ad23 = __floats2half2_rn(ap[2 * NU], ap[3 * NU]);
        __half2 nu2  = __float2half2_rn(nu[tid]);
        uint4 p;
        p.x = *(unsigned*)&ad01;
        p.y = *(unsigned*)&ad23;
        p.z = *(unsigned*)&nu2;
        p.w = 0;
        pk[tid] = p;
    }

    // ---- scores: thread = e, tiles of 32 u from SMEM ----
    float m0 = 0.f, m1 = 0.f, m2 = 0.f, m3 = 0.f;
    for (int t = 0; t < NTILES; ++t) {
        if (t < NTILES - 1)
            stage_tile(sbb[(t + 1) & 1], aeg + (t + 1) * TILE_HALFS, tid);
        if (t < NTILES - 1)
            asm volatile("cp.async.wait_group 1;" ::: "memory");
        else
            asm volatile("cp.async.wait_group 0;" ::: "memory");
        __syncthreads();

        const __half* sa = &buf[t & 1][tid];
        const int u0 = t * UT;
#pragma unroll
        for (int cc = 0; cc < UT; cc += 16) {   // 16-u chunks, fp16 acc
            __half2 a01 = __float2half2_rn(0.f);
            __half2 a23 = __float2half2_rn(0.f);
#pragma unroll
            for (int k = 0; k < 16; k++) {
                __half  a  = sa[(cc + k) << 8];        // LDS.16, conflict-free
                uint4   p  = pk[u0 + cc + k];          // LDS.128 broadcast
                __half2 ah = __half2half2(a);
                __half2 c01 = __hadd2(ah, *(__half2*)&p.x);
                __half2 c23 = __hadd2(ah, *(__half2*)&p.y);
                unsigned t01, t23;
                asm("tanh.approx.f16x2 %0, %1;" : "=r"(t01) : "r"(*(unsigned*)&c01));
                asm("tanh.approx.f16x2 %0, %1;" : "=r"(t23) : "r"(*(unsigned*)&c23));
                a01 = __hfma2(*(__half2*)&t01, *(__half2*)&p.z, a01);
                a23 = __hfma2(*(__half2*)&t23, *(__half2*)&p.z, a23);
            }
            float2 f01 = __half22float2(a01);
            float2 f23 = __half22float2(a23);
            m0 += f01.x; m1 += f01.y; m2 += f23.x; m3 += f23.y;
        }
        __syncthreads();
    }

    // prefetch en tile 0 — latency hides under the softmax math
    stage_tile(sb0, eng, tid);

    // ---- softmax over e for the 4 rows ----
    float mu[4] = {m0, m1, m2, m3};
    float al[4];
#pragma unroll
    for (int tt = 0; tt < 4; tt++) {
        float v  = mu[tt];
        float mx = v;
#pragma unroll
        for (int o = 16; o; o >>= 1) mx = fmaxf(mx, __shfl_xor_sync(0xffffffffu, mx, o));
        if ((tid & 31) == 0) red[tid >> 5] = mx;
        __syncthreads();
        mx = fmaxf(fmaxf(fmaxf(red[0], red[1]), fmaxf(red[2], red[3])),
                   fmaxf(fmaxf(red[4], red[5]), fmaxf(red[6], red[7])));
        __syncthreads();
        float ex = __expf(v - mx);
        float s  = ex;
#pragma unroll
        for (int o = 16; o; o >>= 1) s += __shfl_xor_sync(0xffffffffu, s, o);
        if ((tid & 31) == 0) red[tid >> 5] = s;
        __syncthreads();
        s = ((red[0] + red[1]) + (red[2] + red[3])) + ((red[4] + red[5]) + (red[6] + red[7]));
        __syncthreads();
        al[tt] = __fdividef(ex, s);
    }
    alpha4[tid] = make_float4(al[0], al[1], al[2], al[3]);
    __syncthreads();

    // ---- context: thread = d, tiles of 32 e from SMEM ----
    const float* dep = de + (b * NT + t0) * ND + tid;
    float o0 = dep[0], o1 = dep[ND], o2 = dep[2 * ND], o3 = dep[3 * ND];
    for (int t = 0; t < NTILES; ++t) {
        if (t < NTILES - 1)
            stage_tile(sbb[(t + 1) & 1], eng + (t + 1) * TILE_HALFS, tid);
        if (t < NTILES - 1)
            asm volatile("cp.async.wait_group 1;" ::: "memory");
        else
            asm volatile("cp.async.wait_group 0;" ::: "memory");
        __syncthreads();

        const __half* sv = &buf[t & 1][tid];
        const int e0 = t * UT;
#pragma unroll
        for (int k = 0; k < UT; k++) {
            float  v = __half2float(sv[k << 8]);   // LDS.16, conflict-free
            float4 a = alpha4[e0 + k];             // LDS.128 broadcast
            o0 = fmaf(a.x, v, o0);
            o1 = fmaf(a.y, v, o1);
            o2 = fmaf(a.z, v, o2);
            o3 = fmaf(a.w, v, o3);
        }
        __syncthreads();
    }
    float* op = out + (b * NT + t0) * ND + tid;
    op[0] = o0; op[ND] = o1; op[2 * ND] = o2; op[3 * ND] = o3;
}

extern "C" void kernel_launch(void* const* d_in, const int* in_sizes, int n_in,
                              void* d_out, int out_size)
{
    const float* en   = (const float*)d_in[0];   // (8,256,256)
    const float* de   = (const float*)d_in[1];   // (8,256,256)
    const float* w_en = (const float*)d_in[2];   // (256,256)
    const float* w_de = (const float*)d_in[3];   // (256,256)
    const float* nu   = (const float*)d_in[4];   // (256,1)
    float* out = (float*)d_out;                  // (8,256,256) fp32

    dim3 gg(4, 2, 16);              // 4 n-tiles(64), 2 m-tiles(128), 8 b * 2
    gemm_kernel<<<gg, 256>>>(en, de, w_en, w_de);
    attn_kernel<<<NB * (NT / 4), 256>>>(de, nu, out);
}

// round 9
// speedup vs baseline: 1.4110x; 1.0182x over previous
#include <cuda_runtime.h>
#include <cuda_bf16.h>
#include <cuda_fp16.h>

#define NB 8
#define NT 256   // T_en == T_de
#define ND 256
#define NU 256

// Scratch (device globals: no allocation allowed in kernel_launch)
__device__ __half d_aeT_h[NB * NU * NT];  // aeT[b][u][e] fp16 (e contiguous)
__device__ float  d_ad   [NB * NT * NU];  // ad [b][t][u] fp32
__device__ __half d_en_h [NB * NT * ND];  // en[b][e][d] fp16 (d contiguous)

// ---------------------------------------------------------------------------
// tf32 tensor-core GEMM (mma.sync.m16n8k8).
//   which=0: C[e][u] = sum_d en[b][e][d] * w_en[d][u] -> d_aeT_h[b][u][e] fp16
//            (n0==0 CTAs also emit en as fp16 to d_en_h from the SMEM A tile)
//   which=1: C[t][u] = sum_d de[b][t][d] * w_de[d][u] -> d_ad[b][t][u] fp32
// CTA tile 128(M)x64(N), 8 warps of 32x32, K-chunk 32, register prefetch.
// ---------------------------------------------------------------------------
__device__ __forceinline__ unsigned f2tf(float x)
{
    unsigned r;
    asm("cvt.rna.tf32.f32 %0, %1;" : "=r"(r) : "f"(x));
    return r;
}

__device__ __forceinline__ void mma_tf32(float c[4], const unsigned a[4],
                                         unsigned b0, unsigned b1)
{
    asm volatile(
        "mma.sync.aligned.m16n8k8.row.col.f32.tf32.tf32.f32 "
        "{%0,%1,%2,%3}, {%4,%5,%6,%7}, {%8,%9}, {%0,%1,%2,%3};"
        : "+f"(c[0]), "+f"(c[1]), "+f"(c[2]), "+f"(c[3])
        : "r"(a[0]), "r"(a[1]), "r"(a[2]), "r"(a[3]), "r"(b0), "r"(b1));
}

__global__ __launch_bounds__(256) void gemm_kernel(const float* __restrict__ en,
                                                   const float* __restrict__ de,
                                                   const float* __restrict__ w_en,
                                                   const float* __restrict__ w_de)
{
    const int z     = blockIdx.z;
    const int b     = z >> 1;
    const int which = z & 1;

    const float* A  = which ? (de + b * NT * ND) : (en + b * NT * ND);  // (256,256)
    const float* Bm = which ? w_de : w_en;                               // (256,256)

    const int m0 = blockIdx.y * 128;
    const int n0 = blockIdx.x * 64;

    __shared__ float As[128][36];   // pad 36: A-frag banks (4g+tig) distinct
    __shared__ float Bs[32][68];    // pad 68: B-frag banks (4tig+g) distinct

    const int tid  = threadIdx.x;
    const int w    = tid >> 5;
    const int lane = tid & 31;
    const int g    = lane >> 2;     // group id (0..7)
    const int tig  = lane & 3;      // thread in group
    const int mw   = (w & 3) * 32;  // warp M offset
    const int nw   = (w >> 2) * 32; // warp N offset

    const bool emit_en = (which == 0) && (n0 == 0);

    float c[2][4][4];
#pragma unroll
    for (int mt = 0; mt < 2; mt++)
#pragma unroll
        for (int nt = 0; nt < 4; nt++)
#pragma unroll
            for (int i = 0; i < 4; i++) c[mt][nt][i] = 0.f;

    // prefetch registers: A 4 x float4, B 2 x float4
    float4 pa[4], pb[2];
    const int ar[4] = {tid >> 3, (tid + 256) >> 3, (tid + 512) >> 3, (tid + 768) >> 3};
    const int ac    = (tid & 7) << 2;
    const int br[2] = {tid >> 4, (tid + 256) >> 4};
    const int bc    = (tid & 15) << 2;

#pragma unroll
    for (int i = 0; i < 4; i++)
        pa[i] = *(const float4*)(A + (m0 + ar[i]) * 256 + 0 + ac);
#pragma unroll
    for (int i = 0; i < 2; i++)
        pb[i] = *(const float4*)(Bm + (0 + br[i]) * 256 + n0 + bc);

    for (int t = 0; t < 8; ++t) {
        __syncthreads();
#pragma unroll
        for (int i = 0; i < 4; i++)
            *(float4*)&As[ar[i]][ac] = pa[i];
#pragma unroll
        for (int i = 0; i < 2; i++)
            *(float4*)&Bs[br[i]][bc] = pb[i];
        __syncthreads();

        if (emit_en) {
            // publish this A tile (en) as fp16: rows m0..m0+127, cols t*32..+32
            __half* dst = d_en_h + b * NT * ND;
#pragma unroll
            for (int i = 0; i < 8; i++) {
                int q  = tid + i * 256;          // 2048 half2 per tile
                int r  = q >> 4;
                int c2 = (q & 15) << 1;
                __half2 h = __floats2half2_rn(As[r][c2], As[r][c2 + 1]);
                *(unsigned*)(dst + (m0 + r) * ND + t * 32 + c2) = *(unsigned*)&h;
            }
        }

        if (t < 7) {
            int k0 = (t + 1) * 32;
#pragma unroll
            for (int i = 0; i < 4; i++)
                pa[i] = *(const float4*)(A + (m0 + ar[i]) * 256 + k0 + ac);
#pragma unroll
            for (int i = 0; i < 2; i++)
                pb[i] = *(const float4*)(Bm + (k0 + br[i]) * 256 + n0 + bc);
        }

#pragma unroll
        for (int kt = 0; kt < 4; kt++) {
            unsigned a[2][4];
#pragma unroll
            for (int mt = 0; mt < 2; mt++) {
                int r = mw + mt * 16 + g;
                a[mt][0] = f2tf(As[r][kt * 8 + tig]);
                a[mt][1] = f2tf(As[r + 8][kt * 8 + tig]);
                a[mt][2] = f2tf(As[r][kt * 8 + tig + 4]);
                a[mt][3] = f2tf(As[r + 8][kt * 8 + tig + 4]);
            }
#pragma unroll
            for (int nt = 0; nt < 4; nt++) {
                unsigned b0 = f2tf(Bs[kt * 8 + tig][nw + nt * 8 + g]);
                unsigned b1 = f2tf(Bs[kt * 8 + tig + 4][nw + nt * 8 + g]);
                mma_tf32(c[0][nt], a[0], b0, b1);
                mma_tf32(c[1][nt], a[1], b0, b1);
            }
        }
    }

    if (which == 0) {
        // C[e][u] -> aeT_h[b][u][e] fp16 (transposed scatter, tiny volume)
        __half* dst = d_aeT_h + b * NU * NT;
#pragma unroll
        for (int mt = 0; mt < 2; mt++)
#pragma unroll
            for (int nt = 0; nt < 4; nt++) {
                int e0 = m0 + mw + mt * 16 + g;
                int u0 = n0 + nw + nt * 8 + 2 * tig;
                dst[u0 * NT + e0]           = __float2half(c[mt][nt][0]);
                dst[(u0 + 1) * NT + e0]     = __float2half(c[mt][nt][1]);
                dst[u0 * NT + e0 + 8]       = __float2half(c[mt][nt][2]);
                dst[(u0 + 1) * NT + e0 + 8] = __float2half(c[mt][nt][3]);
            }
    } else {
        float* dst = d_ad + b * NT * NU;
#pragma unroll
        for (int mt = 0; mt < 2; mt++)
#pragma unroll
            for (int nt = 0; nt < 4; nt++) {
                int row = m0 + mw + mt * 16 + g;
                int col = n0 + nw + nt * 8 + 2 * tig;
                *(float2*)(dst + row * NU + col)       = make_float2(c[mt][nt][0], c[mt][nt][1]);
                *(float2*)(dst + (row + 8) * NU + col) = make_float2(c[mt][nt][2], c[mt][nt][3]);
            }
    }
}

// ---------------------------------------------------------------------------
// Fused tanh-score + softmax + context — R4 configuration VERBATIM (best:
// 52.4us, at the MUFU tanh roofline). One CTA = (b, 4 decoder rows),
// CTA-wide 16KB cp.async double-buffered tiles.
// ---------------------------------------------------------------------------
#define UT 32                       // u (or e) values per tile
#define TILE_HALFS (UT * 256)       // 8192 halfs = 16KB
#define NTILES (256 / UT)           // 8

__device__ __forceinline__ void stage_tile(unsigned sbase, const __half* g, int tid)
{
    unsigned s = sbase + tid * 16;
    const char* gp = (const char*)g + tid * 16;
#pragma unroll
    for (int i = 0; i < 4; i++)
        asm volatile("cp.async.cg.shared.global [%0], [%1], 16;\n"
                     :: "r"(s + i * 4096), "l"(gp + i * 4096) : "memory");
    asm volatile("cp.async.commit_group;" ::: "memory");
}

__global__ __launch_bounds__(256) void attn_kernel(const float* __restrict__ de,
                                                   const float* __restrict__ nu,
                                                   float* __restrict__ out)
{
    const int b   = blockIdx.x >> 6;          // 8 b * 64 groups
    const int t0  = (blockIdx.x & 63) << 2;   // 4 decoder rows per CTA
    const int tid = threadIdx.x;

    __shared__ __half buf[2][TILE_HALFS];     // 32KB double buffer
    __shared__ uint4  pk[256];                // {ad01, ad23, nu2, pad} per u
    __shared__ float4 alpha4[256];
    __shared__ float  red[8];

    const unsigned sb0 = (unsigned)__cvta_generic_to_shared(&buf[0][0]);
    const unsigned sb1 = (unsigned)__cvta_generic_to_shared(&buf[1][0]);
    const unsigned sbb[2] = {sb0, sb1};

    const __half* aeg = d_aeT_h + b * NU * NT;   // [u][e] tiles, contiguous
    const __half* eng = d_en_h  + b * NT * ND;   // [e][d] tiles, contiguous

    // prologue: stage ae tile 0; fill pk meanwhile
    stage_tile(sb0, aeg, tid);
    {
        const float* ap = d_ad + (b * NT + t0) * NU + tid;
        __half2 ad01 = __floats2half2_rn(ap[0],      ap[NU]);
        __half2 ad23 = __floats2half2_rn(ap[2 * NU], ap[3 * NU]);
        __half2 nu2  = __float2half2_rn(nu[tid]);
        uint4 p;
        p.x = *(unsigned*)&ad01;
        p.y = *(unsigned*)&ad23;
        p.z = *(unsigned*)&nu2;
        p.w = 0;
        pk[tid] = p;
    }

    // ---- scores: thread = e, tiles of 32 u from SMEM ----
    float m0 = 0.f, m1 = 0.f, m2 = 0.f, m3 = 0.f;
    for (int t = 0; t < NTILES; ++t) {
        if (t < NTILES - 1)
            stage_tile(sbb[(t + 1) & 1], aeg + (t + 1) * TILE_HALFS, tid);
        if (t < NTILES - 1)
            asm volatile("cp.async.wait_group 1;" ::: "memory");
        else
            asm volatile("cp.async.wait_group 0;" ::: "memory");
        __syncthreads();

        const __half* sa = &buf[t & 1][tid];
        const int u0 = t * UT;
#pragma unroll
        for (int cc = 0; cc < UT; cc += 16) {   // 16-u chunks, fp16 acc
            __half2 a01 = __float2half2_rn(0.f);
            __half2 a23 = __float2half2_rn(0.f);
#pragma unroll
            for (int k = 0; k < 16; k++) {
                __half  a  = sa[(cc + k) << 8];        // LDS.16, conflict-free
                uint4   p  = pk[u0 + cc + k];          // LDS.128 broadcast
                __half2 ah = __half2half2(a);
                __half2 c01 = __hadd2(ah, *(__half2*)&p.x);
                __half2 c23 = __hadd2(ah, *(__half2*)&p.y);
                unsigned t01, t23;
                asm("tanh.approx.f16x2 %0, %1;" : "=r"(t01) : "r"(*(unsigned*)&c01));
                asm("tanh.approx.f16x2 %0, %1;" : "=r"(t23) : "r"(*(unsigned*)&c23));
                a01 = __hfma2(*(__half2*)&t01, *(__half2*)&p.z, a01);
                a23 = __hfma2(*(__half2*)&t23, *(__half2*)&p.z, a23);
            }
            float2 f01 = __half22float2(a01);
            float2 f23 = __half22float2(a23);
            m0 += f01.x; m1 += f01.y; m2 += f23.x; m3 += f23.y;
        }
        __syncthreads();
    }

    // prefetch en tile 0 — latency hides under the softmax math
    stage_tile(sb0, eng, tid);

    // ---- softmax over e for the 4 rows ----
    float mu[4] = {m0, m1, m2, m3};
    float al[4];
#pragma unroll
    for (int tt = 0; tt < 4; tt++) {
        float v  = mu[tt];
        float mx = v;
#pragma unroll
        for (int o = 16; o; o >>= 1) mx = fmaxf(mx, __shfl_xor_sync(0xffffffffu, mx, o));
        if ((tid & 31) == 0) red[tid >> 5] = mx;
        __syncthreads();
        mx = fmaxf(fmaxf(fmaxf(red[0], red[1]), fmaxf(red[2], red[3])),
                   fmaxf(fmaxf(red[4], red[5]), fmaxf(red[6], red[7])));
        __syncthreads();
        float ex = __expf(v - mx);
        float s  = ex;
#pragma unroll
        for (int o = 16; o; o >>= 1) s += __shfl_xor_sync(0xffffffffu, s, o);
        if ((tid & 31) == 0) red[tid >> 5] = s;
        __syncthreads();
        s = ((red[0] + red[1]) + (red[2] + red[3])) + ((red[4] + red[5]) + (red[6] + red[7]));
        __syncthreads();
        al[tt] = __fdividef(ex, s);
    }
    alpha4[tid] = make_float4(al[0], al[1], al[2], al[3]);
    __syncthreads();

    // ---- context: thread = d, tiles of 32 e from SMEM ----
    const float* dep = de + (b * NT + t0) * ND + tid;
    float o0 = dep[0], o1 = dep[ND], o2 = dep[2 * ND], o3 = dep[3 * ND];
    for (int t = 0; t < NTILES; ++t) {
        if (t < NTILES - 1)
            stage_tile(sbb[(t + 1) & 1], eng + (t + 1) * TILE_HALFS, tid);
        if (t < NTILES - 1)
            asm volatile("cp.async.wait_group 1;" ::: "memory");
        else
            asm volatile("cp.async.wait_group 0;" ::: "memory");
        __syncthreads();

        const __half* sv = &buf[t & 1][tid];
        const int e0 = t * UT;
#pragma unroll
        for (int k = 0; k < UT; k++) {
            float  v = __half2float(sv[k << 8]);   // LDS.16, conflict-free
            float4 a = alpha4[e0 + k];             // LDS.128 broadcast
            o0 = fmaf(a.x, v, o0);
            o1 = fmaf(a.y, v, o1);
            o2 = fmaf(a.z, v, o2);
            o3 = fmaf(a.w, v, o3);
        }
        __syncthreads();
    }
    float* op = out + (b * NT + t0) * ND + tid;
    op[0] = o0; op[ND] = o1; op[2 * ND] = o2; op[3 * ND] = o3;
}

extern "C" void kernel_launch(void* const* d_in, const int* in_sizes, int n_in,
                              void* d_out, int out_size)
{
    const float* en   = (const float*)d_in[0];   // (8,256,256)
    const float* de   = (const float*)d_in[1];   // (8,256,256)
    const float* w_en = (const float*)d_in[2];   // (256,256)
    const float* w_de = (const float*)d_in[3];   // (256,256)
    const float* nu   = (const float*)d_in[4];   // (256,1)
    float* out = (float*)d_out;                  // (8,256,256) fp32

    dim3 gg(4, 2, 16);              // 4 n-tiles(64), 2 m-tiles(128), 8 b * 2
    gemm_kernel<<<gg, 256>>>(en, de, w_en, w_de);
    attn_kernel<<<NB * (NT / 4), 256>>>(de, nu, out);
}

// round 10
// speedup vs baseline: 1.5077x; 1.0685x over previous
#include <cuda_runtime.h>
#include <cuda_bf16.h>
#include <cuda_fp16.h>

#define NB 8
#define NT 256
#define ND 256
#define NU 256

__device__ __half d_aeT_h[NB * NU * NT];  // aeT[b][u][e] fp16
__device__ float  d_ad   [NB * NT * NU];  // ad [b][t][u] fp32
__device__ __half d_en_h [NB * NT * ND];  // en[b][e][d] fp16

// ---------------------------------------------------------------------------
// tf32 tensor-core GEMM (unchanged from R8; ~7us)
// ---------------------------------------------------------------------------
__device__ __forceinline__ unsigned f2tf(float x)
{
    unsigned r;
    asm("cvt.rna.tf32.f32 %0, %1;" : "=r"(r) : "f"(x));
    return r;
}

__device__ __forceinline__ void mma_tf32(float c[4], const unsigned a[4],
                                         unsigned b0, unsigned b1)
{
    asm volatile(
        "mma.sync.aligned.m16n8k8.row.col.f32.tf32.tf32.f32 "
        "{%0,%1,%2,%3}, {%4,%5,%6,%7}, {%8,%9}, {%0,%1,%2,%3};"
        : "+f"(c[0]), "+f"(c[1]), "+f"(c[2]), "+f"(c[3])
        : "r"(a[0]), "r"(a[1]), "r"(a[2]), "r"(a[3]), "r"(b0), "r"(b1));
}

__global__ __launch_bounds__(256) void gemm_kernel(const float* __restrict__ en,
                                                   const float* __restrict__ de,
                                                   const float* __restrict__ w_en,
                                                   const float* __restrict__ w_de)
{
    const int z     = blockIdx.z;
    const int b     = z >> 1;
    const int which = z & 1;

    const float* A  = which ? (de + b * NT * ND) : (en + b * NT * ND);
    const float* Bm = which ? w_de : w_en;

    const int m0 = blockIdx.y * 128;
    const int n0 = blockIdx.x * 64;

    __shared__ float As[128][36];
    __shared__ float Bs[32][68];

    const int tid  = threadIdx.x;
    const int w    = tid >> 5;
    const int lane = tid & 31;
    const int g    = lane >> 2;
    const int tig  = lane & 3;
    const int mw   = (w & 3) * 32;
    const int nw   = (w >> 2) * 32;

    const bool emit_en = (which == 0) && (n0 == 0);

    float c[2][4][4];
#pragma unroll
    for (int mt = 0; mt < 2; mt++)
#pragma unroll
        for (int nt = 0; nt < 4; nt++)
#pragma unroll
            for (int i = 0; i < 4; i++) c[mt][nt][i] = 0.f;

    float4 pa[4], pb[2];
    const int ar[4] = {tid >> 3, (tid + 256) >> 3, (tid + 512) >> 3, (tid + 768) >> 3};
    const int ac    = (tid & 7) << 2;
    const int br[2] = {tid >> 4, (tid + 256) >> 4};
    const int bc    = (tid & 15) << 2;

#pragma unroll
    for (int i = 0; i < 4; i++)
        pa[i] = *(const float4*)(A + (m0 + ar[i]) * 256 + 0 + ac);
#pragma unroll
    for (int i = 0; i < 2; i++)
        pb[i] = *(const float4*)(Bm + (0 + br[i]) * 256 + n0 + bc);

    for (int t = 0; t < 8; ++t) {
        __syncthreads();
#pragma unroll
        for (int i = 0; i < 4; i++)
            *(float4*)&As[ar[i]][ac] = pa[i];
#pragma unroll
        for (int i = 0; i < 2; i++)
            *(float4*)&Bs[br[i]][bc] = pb[i];
        __syncthreads();

        if (emit_en) {
            __half* dst = d_en_h + b * NT * ND;
#pragma unroll
            for (int i = 0; i < 8; i++) {
                int q  = tid + i * 256;
                int r  = q >> 4;
                int c2 = (q & 15) << 1;
                __half2 h = __floats2half2_rn(As[r][c2], As[r][c2 + 1]);
                *(unsigned*)(dst + (m0 + r) * ND + t * 32 + c2) = *(unsigned*)&h;
            }
        }

        if (t < 7) {
            int k0 = (t + 1) * 32;
#pragma unroll
            for (int i = 0; i < 4; i++)
                pa[i] = *(const float4*)(A + (m0 + ar[i]) * 256 + k0 + ac);
#pragma unroll
            for (int i = 0; i < 2; i++)
                pb[i] = *(const float4*)(Bm + (k0 + br[i]) * 256 + n0 + bc);
        }

#pragma unroll
        for (int kt = 0; kt < 4; kt++) {
            unsigned a[2][4];
#pragma unroll
            for (int mt = 0; mt < 2; mt++) {
                int r = mw + mt * 16 + g;
                a[mt][0] = f2tf(As[r][kt * 8 + tig]);
                a[mt][1] = f2tf(As[r + 8][kt * 8 + tig]);
                a[mt][2] = f2tf(As[r][kt * 8 + tig + 4]);
                a[mt][3] = f2tf(As[r + 8][kt * 8 + tig + 4]);
            }
#pragma unroll
            for (int nt = 0; nt < 4; nt++) {
                unsigned b0 = f2tf(Bs[kt * 8 + tig][nw + nt * 8 + g]);
                unsigned b1 = f2tf(Bs[kt * 8 + tig + 4][nw + nt * 8 + g]);
                mma_tf32(c[0][nt], a[0], b0, b1);
                mma_tf32(c[1][nt], a[1], b0, b1);
            }
        }
    }

    if (which == 0) {
        __half* dst = d_aeT_h + b * NU * NT;
#pragma unroll
        for (int mt = 0; mt < 2; mt++)
#pragma unroll
            for (int nt = 0; nt < 4; nt++) {
                int e0 = m0 + mw + mt * 16 + g;
                int u0 = n0 + nw + nt * 8 + 2 * tig;
                dst[u0 * NT + e0]           = __float2half(c[mt][nt][0]);
                dst[(u0 + 1) * NT + e0]     = __float2half(c[mt][nt][1]);
                dst[u0 * NT + e0 + 8]       = __float2half(c[mt][nt][2]);
                dst[(u0 + 1) * NT + e0 + 8] = __float2half(c[mt][nt][3]);
            }
    } else {
        float* dst = d_ad + b * NT * NU;
#pragma unroll
        for (int mt = 0; mt < 2; mt++)
#pragma unroll
            for (int nt = 0; nt < 4; nt++) {
                int row = m0 + mw + mt * 16 + g;
                int col = n0 + nw + nt * 8 + 2 * tig;
                *(float2*)(dst + row * NU + col)       = make_float2(c[mt][nt][0], c[mt][nt][1]);
                *(float2*)(dst + (row + 8) * NU + col) = make_float2(c[mt][nt][2], c[mt][nt][3]);
            }
    }
}

// ---------------------------------------------------------------------------
// Attn kernel: R4 staging; score loop splits each 32-u tile into 22 u on the
// MUFU tanh path + 10 u on an fp16 polynomial (FMA pipe), interleaved m,m,p
// so both pipes are fed from one instruction stream.
// ---------------------------------------------------------------------------
#define UT 32
#define TILE_HALFS (UT * 256)
#define NTILES (256 / UT)

__device__ __forceinline__ void stage_tile(unsigned sbase, const __half* g, int tid)
{
    unsigned s = sbase + tid * 16;
    const char* gp = (const char*)g + tid * 16;
#pragma unroll
    for (int i = 0; i < 4; i++)
        asm volatile("cp.async.cg.shared.global [%0], [%1], 16;\n"
                     :: "r"(s + i * 4096), "l"(gp + i * 4096) : "memory");
    asm volatile("cp.async.commit_group;" ::: "memory");
}

// odd poly tanh: x*(c0 + c1 z + ... + c5 z^5), z=x^2, |x| clamped to 3.398
struct PC { __half2 c0, c1, c2, c3, c4, c5, cl; };

__device__ __forceinline__ __half2 ptanh(__half2 x, const PC& P)
{
    __half2 xc = __hmax2(__hmin2(x, P.cl), __hneg2(P.cl));
    __half2 z  = __hmul2(xc, xc);
    __half2 h  = __hfma2(P.c5, z, P.c4);
    h = __hfma2(h, z, P.c3);
    h = __hfma2(h, z, P.c2);
    h = __hfma2(h, z, P.c1);
    h = __hfma2(h, z, P.c0);
    return __hmul2(xc, h);
}

__global__ __launch_bounds__(256) void attn_kernel(const float* __restrict__ de,
                                                   const float* __restrict__ nu,
                                                   float* __restrict__ out)
{
    const int b   = blockIdx.x >> 6;
    const int t0  = (blockIdx.x & 63) << 2;
    const int tid = threadIdx.x;

    __shared__ __half buf[2][TILE_HALFS];
    __shared__ uint4  pk[256];
    __shared__ float4 alpha4[256];
    __shared__ float  red[8];

    const unsigned sb0 = (unsigned)__cvta_generic_to_shared(&buf[0][0]);
    const unsigned sb1 = (unsigned)__cvta_generic_to_shared(&buf[1][0]);
    const unsigned sbb[2] = {sb0, sb1};

    const __half* aeg = d_aeT_h + b * NU * NT;
    const __half* eng = d_en_h  + b * NT * ND;

    PC P;
    P.c0 = __float2half2_rn(0.992381f);
    P.c1 = __float2half2_rn(-0.282962f);
    P.c2 = __float2half2_rn(0.065192f);
    P.c3 = __float2half2_rn(-0.0087342f);
    P.c4 = __float2half2_rn(0.00059761f);
    P.c5 = __float2half2_rn(-1.6085e-5f);
    P.cl = __float2half2_rn(3.398f);

    stage_tile(sb0, aeg, tid);
    {
        const float* ap = d_ad + (b * NT + t0) * NU + tid;
        __half2 ad01 = __floats2half2_rn(ap[0],      ap[NU]);
        __half2 ad23 = __floats2half2_rn(ap[2 * NU], ap[3 * NU]);
        __half2 nu2  = __float2half2_rn(nu[tid]);
        uint4 p;
        p.x = *(unsigned*)&ad01;
        p.y = *(unsigned*)&ad23;
        p.z = *(unsigned*)&nu2;
        p.w = 0;
        pk[tid] = p;
    }

    // ---- scores ----
    float m0 = 0.f, m1 = 0.f, m2 = 0.f, m3 = 0.f;
    for (int t = 0; t < NTILES; ++t) {
        if (t < NTILES - 1)
            stage_tile(sbb[(t + 1) & 1], aeg + (t + 1) * TILE_HALFS, tid);
        if (t < NTILES - 1)
            asm volatile("cp.async.wait_group 1;" ::: "memory");
        else
            asm volatile("cp.async.wait_group 0;" ::: "memory");
        __syncthreads();

        const __half* sa = &buf[t & 1][tid];
        const int u0 = t * UT;

        __half2 am01 = __float2half2_rn(0.f);   // MUFU-path accumulators
        __half2 am23 = __float2half2_rn(0.f);
        __half2 ap01 = __float2half2_rn(0.f);   // poly-path accumulators
        __half2 ap23 = __float2half2_rn(0.f);

        // 22 MUFU u's (k=0..21) + 10 poly u's (k=22..31), interleaved m,m,p
#pragma unroll
        for (int i = 0; i < 11; i++) {
            // MUFU u = 2i
            {
                int k = 2 * i;
                __half  a  = sa[k << 8];
                uint4   p  = pk[u0 + k];
                __half2 ah = __half2half2(a);
                __half2 c01 = __hadd2(ah, *(__half2*)&p.x);
                __half2 c23 = __hadd2(ah, *(__half2*)&p.y);
                unsigned t01, t23;
                asm("tanh.approx.f16x2 %0, %1;" : "=r"(t01) : "r"(*(unsigned*)&c01));
                asm("tanh.approx.f16x2 %0, %1;" : "=r"(t23) : "r"(*(unsigned*)&c23));
                am01 = __hfma2(*(__half2*)&t01, *(__half2*)&p.z, am01);
                am23 = __hfma2(*(__half2*)&t23, *(__half2*)&p.z, am23);
            }
            // MUFU u = 2i+1
            {
                int k = 2 * i + 1;
                __half  a  = sa[k << 8];
                uint4   p  = pk[u0 + k];
                __half2 ah = __half2half2(a);
                __half2 c01 = __hadd2(ah, *(__half2*)&p.x);
                __half2 c23 = __hadd2(ah, *(__half2*)&p.y);
                unsigned t01, t23;
                asm("tanh.approx.f16x2 %0, %1;" : "=r"(t01) : "r"(*(unsigned*)&c01));
                asm("tanh.approx.f16x2 %0, %1;" : "=r"(t23) : "r"(*(unsigned*)&c23));
                am01 = __hfma2(*(__half2*)&t01, *(__half2*)&p.z, am01);
                am23 = __hfma2(*(__half2*)&t23, *(__half2*)&p.z, am23);
            }
            // poly u = 22+i (only 10 of them)
            if (i < 10) {
                int k = 22 + i;
                __half  a  = sa[k << 8];
                uint4   p  = pk[u0 + k];
                __half2 ah = __half2half2(a);
                __half2 c01 = __hadd2(ah, *(__half2*)&p.x);
                __half2 c23 = __hadd2(ah, *(__half2*)&p.y);
                __half2 t01 = ptanh(c01, P);
                __half2 t23 = ptanh(c23, P);
                ap01 = __hfma2(t01, *(__half2*)&p.z, ap01);
                ap23 = __hfma2(t23, *(__half2*)&p.z, ap23);
            }
        }
        float2 f01 = __half22float2(am01);
        float2 f23 = __half22float2(am23);
        float2 g01 = __half22float2(ap01);
        float2 g23 = __half22float2(ap23);
        m0 += f01.x + g01.x; m1 += f01.y + g01.y;
        m2 += f23.x + g23.x; m3 += f23.y + g23.y;
        __syncthreads();
    }

    stage_tile(sb0, eng, tid);   // prefetch en tile 0 under softmax

    // ---- softmax ----
    float mu[4] = {m0, m1, m2, m3};
    float al[4];
#pragma unroll
    for (int tt = 0; tt < 4; tt++) {
        float v  = mu[tt];
        float mx = v;
#pragma unroll
        for (int o = 16; o; o >>= 1) mx = fmaxf(mx, __shfl_xor_sync(0xffffffffu, mx, o));
        if ((tid & 31) == 0) red[tid >> 5] = mx;
        __syncthreads();
        mx = fmaxf(fmaxf(fmaxf(red[0], red[1]), fmaxf(red[2], red[3])),
                   fmaxf(fmaxf(red[4], red[5]), fmaxf(red[6], red[7])));
        __syncthreads();
        float ex = __expf(v - mx);
        float s  = ex;
#pragma unroll
        for (int o = 16; o; o >>= 1) s += __shfl_xor_sync(0xffffffffu, s, o);
        if ((tid & 31) == 0) red[tid >> 5] = s;
        __syncthreads();
        s = ((red[0] + red[1]) + (red[2] + red[3])) + ((red[4] + red[5]) + (red[6] + red[7]));
        __syncthreads();
        al[tt] = __fdividef(ex, s);
    }
    alpha4[tid] = make_float4(al[0], al[1], al[2], al[3]);
    __syncthreads();

    // ---- context ----
    const float* dep = de + (b * NT + t0) * ND + tid;
    float o0 = dep[0], o1 = dep[ND], o2 = dep[2 * ND], o3 = dep[3 * ND];
    for (int t = 0; t < NTILES; ++t) {
        if (t < NTILES - 1)
            stage_tile(sbb[(t + 1) & 1], eng + (t + 1) * TILE_HALFS, tid);
        if (t < NTILES - 1)
            asm volatile("cp.async.wait_group 1;" ::: "memory");
        else
            asm volatile("cp.async.wait_group 0;" ::: "memory");
        __syncthreads();

        const __half* sv = &buf[t & 1][tid];
        const int e0 = t * UT;
#pragma unroll
        for (int k = 0; k < UT; k++) {
            float  v = __half2float(sv[k << 8]);
            float4 a = alpha4[e0 + k];
            o0 = fmaf(a.x, v, o0);
            o1 = fmaf(a.y, v, o1);
            o2 = fmaf(a.z, v, o2);
            o3 = fmaf(a.w, v, o3);
        }
        __syncthreads();
    }
    float* op = out + (b * NT + t0) * ND + tid;
    op[0] = o0; op[ND] = o1; op[2 * ND] = o2; op[3 * ND] = o3;
}

extern "C" void kernel_launch(void* const* d_in, const int* in_sizes, int n_in,
                              void* d_out, int out_size)
{
    const float* en   = (const float*)d_in[0];
    const float* de   = (const float*)d_in[1];
    const float* w_en = (const float*)d_in[2];
    const float* w_de = (const float*)d_in[3];
    const float* nu   = (const float*)d_in[4];
    float* out = (float*)d_out;

    dim3 gg(4, 2, 16);
    gemm_kernel<<<gg, 256>>>(en, de, w_en, w_de);
    attn_kernel<<<NB * (NT / 4), 256>>>(de, nu, out);
}

// round 11
// speedup vs baseline: 1.5649x; 1.0379x over previous
#include <cuda_runtime.h>
#include <cuda_bf16.h>
#include <cuda_fp16.h>

#define NB 8
#define NT 256
#define ND 256
#define NU 256

__device__ __half d_aeT_h[NB * NU * NT];  // aeT[b][u][e] fp16
__device__ float  d_ad   [NB * NT * NU];  // ad [b][t][u] fp32
__device__ __half d_en_h [NB * NT * ND];  // en[b][e][d] fp16

// ---------------------------------------------------------------------------
// tf32 tensor-core GEMM (unchanged from R8; ~7us)
// ---------------------------------------------------------------------------
__device__ __forceinline__ unsigned f2tf(float x)
{
    unsigned r;
    asm("cvt.rna.tf32.f32 %0, %1;" : "=r"(r) : "f"(x));
    return r;
}

__device__ __forceinline__ void mma_tf32(float c[4], const unsigned a[4],
                                         unsigned b0, unsigned b1)
{
    asm volatile(
        "mma.sync.aligned.m16n8k8.row.col.f32.tf32.tf32.f32 "
        "{%0,%1,%2,%3}, {%4,%5,%6,%7}, {%8,%9}, {%0,%1,%2,%3};"
        : "+f"(c[0]), "+f"(c[1]), "+f"(c[2]), "+f"(c[3])
        : "r"(a[0]), "r"(a[1]), "r"(a[2]), "r"(a[3]), "r"(b0), "r"(b1));
}

__global__ __launch_bounds__(256) void gemm_kernel(const float* __restrict__ en,
                                                   const float* __restrict__ de,
                                                   const float* __restrict__ w_en,
                                                   const float* __restrict__ w_de)
{
    const int z     = blockIdx.z;
    const int b     = z >> 1;
    const int which = z & 1;

    const float* A  = which ? (de + b * NT * ND) : (en + b * NT * ND);
    const float* Bm = which ? w_de : w_en;

    const int m0 = blockIdx.y * 128;
    const int n0 = blockIdx.x * 64;

    __shared__ float As[128][36];
    __shared__ float Bs[32][68];

    const int tid  = threadIdx.x;
    const int w    = tid >> 5;
    const int lane = tid & 31;
    const int g    = lane >> 2;
    const int tig  = lane & 3;
    const int mw   = (w & 3) * 32;
    const int nw   = (w >> 2) * 32;

    const bool emit_en = (which == 0) && (n0 == 0);

    float c[2][4][4];
#pragma unroll
    for (int mt = 0; mt < 2; mt++)
#pragma unroll
        for (int nt = 0; nt < 4; nt++)
#pragma unroll
            for (int i = 0; i < 4; i++) c[mt][nt][i] = 0.f;

    float4 pa[4], pb[2];
    const int ar[4] = {tid >> 3, (tid + 256) >> 3, (tid + 512) >> 3, (tid + 768) >> 3};
    const int ac    = (tid & 7) << 2;
    const int br[2] = {tid >> 4, (tid + 256) >> 4};
    const int bc    = (tid & 15) << 2;

#pragma unroll
    for (int i = 0; i < 4; i++)
        pa[i] = *(const float4*)(A + (m0 + ar[i]) * 256 + 0 + ac);
#pragma unroll
    for (int i = 0; i < 2; i++)
        pb[i] = *(const float4*)(Bm + (0 + br[i]) * 256 + n0 + bc);

    for (int t = 0; t < 8; ++t) {
        __syncthreads();
#pragma unroll
        for (int i = 0; i < 4; i++)
            *(float4*)&As[ar[i]][ac] = pa[i];
#pragma unroll
        for (int i = 0; i < 2; i++)
            *(float4*)&Bs[br[i]][bc] = pb[i];
        __syncthreads();

        if (emit_en) {
            __half* dst = d_en_h + b * NT * ND;
#pragma unroll
            for (int i = 0; i < 8; i++) {
                int q  = tid + i * 256;
                int r  = q >> 4;
                int c2 = (q & 15) << 1;
                __half2 h = __floats2half2_rn(As[r][c2], As[r][c2 + 1]);
                *(unsigned*)(dst + (m0 + r) * ND + t * 32 + c2) = *(unsigned*)&h;
            }
        }

        if (t < 7) {
            int k0 = (t + 1) * 32;
#pragma unroll
            for (int i = 0; i < 4; i++)
                pa[i] = *(const float4*)(A + (m0 + ar[i]) * 256 + k0 + ac);
#pragma unroll
            for (int i = 0; i < 2; i++)
                pb[i] = *(const float4*)(Bm + (k0 + br[i]) * 256 + n0 + bc);
        }

#pragma unroll
        for (int kt = 0; kt < 4; kt++) {
            unsigned a[2][4];
#pragma unroll
            for (int mt = 0; mt < 2; mt++) {
                int r = mw + mt * 16 + g;
                a[mt][0] = f2tf(As[r][kt * 8 + tig]);
                a[mt][1] = f2tf(As[r + 8][kt * 8 + tig]);
                a[mt][2] = f2tf(As[r][kt * 8 + tig + 4]);
                a[mt][3] = f2tf(As[r + 8][kt * 8 + tig + 4]);
            }
#pragma unroll
            for (int nt = 0; nt < 4; nt++) {
                unsigned b0 = f2tf(Bs[kt * 8 + tig][nw + nt * 8 + g]);
                unsigned b1 = f2tf(Bs[kt * 8 + tig + 4][nw + nt * 8 + g]);
                mma_tf32(c[0][nt], a[0], b0, b1);
                mma_tf32(c[1][nt], a[1], b0, b1);
            }
        }
    }

    if (which == 0) {
        __half* dst = d_aeT_h + b * NU * NT;
#pragma unroll
        for (int mt = 0; mt < 2; mt++)
#pragma unroll
            for (int nt = 0; nt < 4; nt++) {
                int e0 = m0 + mw + mt * 16 + g;
                int u0 = n0 + nw + nt * 8 + 2 * tig;
                dst[u0 * NT + e0]           = __float2half(c[mt][nt][0]);
                dst[(u0 + 1) * NT + e0]     = __float2half(c[mt][nt][1]);
                dst[u0 * NT + e0 + 8]       = __float2half(c[mt][nt][2]);
                dst[(u0 + 1) * NT + e0 + 8] = __float2half(c[mt][nt][3]);
            }
    } else {
        float* dst = d_ad + b * NT * NU;
#pragma unroll
        for (int mt = 0; mt < 2; mt++)
#pragma unroll
            for (int nt = 0; nt < 4; nt++) {
                int row = m0 + mw + mt * 16 + g;
                int col = n0 + nw + nt * 8 + 2 * tig;
                *(float2*)(dst + row * NU + col)       = make_float2(c[mt][nt][0], c[mt][nt][1]);
                *(float2*)(dst + (row + 8) * NU + col) = make_float2(c[mt][nt][2], c[mt][nt][3]);
            }
    }
}

// ---------------------------------------------------------------------------
// Attn kernel. Score loop: per 32-u tile, 19 u on MUFU tanh (rt16 => 608 cyc)
// + 13 u on fp16 poly (FMA pipe, ~620 cyc) — pipes balanced. Context loop:
// HFMA2 packed accumulation (halved FMA cost).
// ---------------------------------------------------------------------------
#define UT 32
#define TILE_HALFS (UT * 256)
#define NTILES (256 / UT)
#define NM 19     // MUFU u's per tile (rest on poly path)

__device__ __forceinline__ void stage_tile(unsigned sbase, const __half* g, int tid)
{
    unsigned s = sbase + tid * 16;
    const char* gp = (const char*)g + tid * 16;
#pragma unroll
    for (int i = 0; i < 4; i++)
        asm volatile("cp.async.cg.shared.global [%0], [%1], 16;\n"
                     :: "r"(s + i * 4096), "l"(gp + i * 4096) : "memory");
    asm volatile("cp.async.commit_group;" ::: "memory");
}

// odd poly tanh: x*(c0 + c1 z + ... + c5 z^5), z=x^2, |x| clamped to 3.398
struct PC { __half2 c0, c1, c2, c3, c4, c5, cl; };

__device__ __forceinline__ __half2 ptanh(__half2 x, const PC& P)
{
    __half2 xc = __hmax2(__hmin2(x, P.cl), __hneg2(P.cl));
    __half2 z  = __hmul2(xc, xc);
    __half2 h  = __hfma2(P.c5, z, P.c4);
    h = __hfma2(h, z, P.c3);
    h = __hfma2(h, z, P.c2);
    h = __hfma2(h, z, P.c1);
    h = __hfma2(h, z, P.c0);
    return __hmul2(xc, h);
}

__global__ __launch_bounds__(256) void attn_kernel(const float* __restrict__ de,
                                                   const float* __restrict__ nu,
                                                   float* __restrict__ out)
{
    const int b   = blockIdx.x >> 6;
    const int t0  = (blockIdx.x & 63) << 2;
    const int tid = threadIdx.x;

    __shared__ __half buf[2][TILE_HALFS];
    __shared__ uint4  pk[256];
    __shared__ uint2  alpha_h[256];   // {half2(a0,a1), half2(a2,a3)} per e
    __shared__ float  red[8];

    const unsigned sb0 = (unsigned)__cvta_generic_to_shared(&buf[0][0]);
    const unsigned sb1 = (unsigned)__cvta_generic_to_shared(&buf[1][0]);
    const unsigned sbb[2] = {sb0, sb1};

    const __half* aeg = d_aeT_h + b * NU * NT;
    const __half* eng = d_en_h  + b * NT * ND;

    PC P;
    P.c0 = __float2half2_rn(0.992381f);
    P.c1 = __float2half2_rn(-0.282962f);
    P.c2 = __float2half2_rn(0.065192f);
    P.c3 = __float2half2_rn(-0.0087342f);
    P.c4 = __float2half2_rn(0.00059761f);
    P.c5 = __float2half2_rn(-1.6085e-5f);
    P.cl = __float2half2_rn(3.398f);

    stage_tile(sb0, aeg, tid);
    {
        const float* ap = d_ad + (b * NT + t0) * NU + tid;
        __half2 ad01 = __floats2half2_rn(ap[0],      ap[NU]);
        __half2 ad23 = __floats2half2_rn(ap[2 * NU], ap[3 * NU]);
        __half2 nu2  = __float2half2_rn(nu[tid]);
        uint4 p;
        p.x = *(unsigned*)&ad01;
        p.y = *(unsigned*)&ad23;
        p.z = *(unsigned*)&nu2;
        p.w = 0;
        pk[tid] = p;
    }

    // ---- scores: 19 MUFU + 13 poly u's per tile, interleaved ----
    float m0 = 0.f, m1 = 0.f, m2 = 0.f, m3 = 0.f;
    for (int t = 0; t < NTILES; ++t) {
        if (t < NTILES - 1)
            stage_tile(sbb[(t + 1) & 1], aeg + (t + 1) * TILE_HALFS, tid);
        if (t < NTILES - 1)
            asm volatile("cp.async.wait_group 1;" ::: "memory");
        else
            asm volatile("cp.async.wait_group 0;" ::: "memory");
        __syncthreads();

        const __half* sa = &buf[t & 1][tid];
        const int u0 = t * UT;

        __half2 am01 = __float2half2_rn(0.f);
        __half2 am23 = __float2half2_rn(0.f);
        __half2 ap01 = __float2half2_rn(0.f);
        __half2 ap23 = __float2half2_rn(0.f);

#pragma unroll
        for (int i = 0; i < NM; i++) {
            // MUFU u = i
            {
                __half  a  = sa[i << 8];
                uint4   p  = pk[u0 + i];
                __half2 ah = __half2half2(a);
                __half2 c01 = __hadd2(ah, *(__half2*)&p.x);
                __half2 c23 = __hadd2(ah, *(__half2*)&p.y);
                unsigned t01, t23;
                asm("tanh.approx.f16x2 %0, %1;" : "=r"(t01) : "r"(*(unsigned*)&c01));
                asm("tanh.approx.f16x2 %0, %1;" : "=r"(t23) : "r"(*(unsigned*)&c23));
                am01 = __hfma2(*(__half2*)&t01, *(__half2*)&p.z, am01);
                am23 = __hfma2(*(__half2*)&t23, *(__half2*)&p.z, am23);
            }
            // poly u = NM+i (13 of them)
            if (i < UT - NM) {
                int k = NM + i;
                __half  a  = sa[k << 8];
                uint4   p  = pk[u0 + k];
                __half2 ah = __half2half2(a);
                __half2 c01 = __hadd2(ah, *(__half2*)&p.x);
                __half2 c23 = __hadd2(ah, *(__half2*)&p.y);
                __half2 t01 = ptanh(c01, P);
                __half2 t23 = ptanh(c23, P);
                ap01 = __hfma2(t01, *(__half2*)&p.z, ap01);
                ap23 = __hfma2(t23, *(__half2*)&p.z, ap23);
            }
        }
        float2 f01 = __half22float2(am01);
        float2 f23 = __half22float2(am23);
        float2 g01 = __half22float2(ap01);
        float2 g23 = __half22float2(ap23);
        m0 += f01.x + g01.x; m1 += f01.y + g01.y;
        m2 += f23.x + g23.x; m3 += f23.y + g23.y;
        __syncthreads();
    }

    stage_tile(sb0, eng, tid);   // prefetch en tile 0 under softmax

    // ---- softmax ----
    float mu[4] = {m0, m1, m2, m3};
    float al[4];
#pragma unroll
    for (int tt = 0; tt < 4; tt++) {
        float v  = mu[tt];
        float mx = v;
#pragma unroll
        for (int o = 16; o; o >>= 1) mx = fmaxf(mx, __shfl_xor_sync(0xffffffffu, mx, o));
        if ((tid & 31) == 0) red[tid >> 5] = mx;
        __syncthreads();
        mx = fmaxf(fmaxf(fmaxf(red[0], red[1]), fmaxf(red[2], red[3])),
                   fmaxf(fmaxf(red[4], red[5]), fmaxf(red[6], red[7])));
        __syncthreads();
        float ex = __expf(v - mx);
        float s  = ex;
#pragma unroll
        for (int o = 16; o; o >>= 1) s += __shfl_xor_sync(0xffffffffu, s, o);
        if ((tid & 31) == 0) red[tid >> 5] = s;
        __syncthreads();
        s = ((red[0] + red[1]) + (red[2] + red[3])) + ((red[4] + red[5]) + (red[6] + red[7]));
        __syncthreads();
        al[tt] = __fdividef(ex, s);
    }
    {
        __half2 al01 = __floats2half2_rn(al[0], al[1]);
        __half2 al23 = __floats2half2_rn(al[2], al[3]);
        uint2 av;
        av.x = *(unsigned*)&al01;
        av.y = *(unsigned*)&al23;
        alpha_h[tid] = av;
    }
    __syncthreads();

    // ---- context: HFMA2 packed accumulation, fp32 carry per tile ----
    const float* dep = de + (b * NT + t0) * ND + tid;
    float o0 = dep[0], o1 = dep[ND], o2 = dep[2 * ND], o3 = dep[3 * ND];
    for (int t = 0; t < NTILES; ++t) {
        if (t < NTILES - 1)
            stage_tile(sbb[(t + 1) & 1], eng + (t + 1) * TILE_HALFS, tid);
        if (t < NTILES - 1)
            asm volatile("cp.async.wait_group 1;" ::: "memory");
        else
            asm volatile("cp.async.wait_group 0;" ::: "memory");
        __syncthreads();

        const __half* sv = &buf[t & 1][tid];
        const int e0 = t * UT;
        __half2 acc01 = __float2half2_rn(0.f);
        __half2 acc23 = __float2half2_rn(0.f);
#pragma unroll
        for (int k = 0; k < UT; k++) {
            __half2 v2 = __half2half2(sv[k << 8]);   // LDS.16
            uint2   a  = alpha_h[e0 + k];            // LDS.64 broadcast
            acc01 = __hfma2(*(__half2*)&a.x, v2, acc01);
            acc23 = __hfma2(*(__half2*)&a.y, v2, acc23);
        }
        float2 f01 = __half22float2(acc01);
        float2 f23 = __half22float2(acc23);
        o0 += f01.x; o1 += f01.y; o2 += f23.x; o3 += f23.y;
        __syncthreads();
    }
    float* op = out + (b * NT + t0) * ND + tid;
    op[0] = o0; op[ND] = o1; op[2 * ND] = o2; op[3 * ND] = o3;
}

extern "C" void kernel_launch(void* const* d_in, const int* in_sizes, int n_in,
                              void* d_out, int out_size)
{
    const float* en   = (const float*)d_in[0];
    const float* de   = (const float*)d_in[1];
    const float* w_en = (const float*)d_in[2];
    const float* w_de = (const float*)d_in[3];
    const float* nu   = (const float*)d_in[4];
    float* out = (float*)d_out;

    dim3 gg(4, 2, 16);
    gemm_kernel<<<gg, 256>>>(en, de, w_en, w_de);
    attn_kernel<<<NB * (NT / 4), 256>>>(de, nu, out);
}

// round 12
// speedup vs baseline: 1.5724x; 1.0048x over previous
#include <cuda_runtime.h>
#include <cuda_bf16.h>
#include <cuda_fp16.h>

#define NB 8
#define NT 256
#define ND 256
#define NU 256

__device__ __half d_aeT_h[NB * NU * NT];  // aeT[b][u][e] fp16
__device__ float  d_ad   [NB * NT * NU];  // ad [b][t][u] fp32
__device__ float  d_alpha[NB * NT * NT];  // alpha[b][t][e] fp32

// ---------------------------------------------------------------------------
// tf32 MMA helpers
// ---------------------------------------------------------------------------
__device__ __forceinline__ unsigned f2tf(float x)
{
    unsigned r;
    asm("cvt.rna.tf32.f32 %0, %1;" : "=r"(r) : "f"(x));
    return r;
}

__device__ __forceinline__ void mma_tf32(float c[4], const unsigned a[4],
                                         unsigned b0, unsigned b1)
{
    asm volatile(
        "mma.sync.aligned.m16n8k8.row.col.f32.tf32.tf32.f32 "
        "{%0,%1,%2,%3}, {%4,%5,%6,%7}, {%8,%9}, {%0,%1,%2,%3};"
        : "+f"(c[0]), "+f"(c[1]), "+f"(c[2]), "+f"(c[3])
        : "r"(a[0]), "r"(a[1]), "r"(a[2]), "r"(a[3]), "r"(b0), "r"(b1));
}

// ---------------------------------------------------------------------------
// Front GEMM (tf32): att_en -> d_aeT_h (fp16, transposed), att_de -> d_ad.
// ---------------------------------------------------------------------------
__global__ __launch_bounds__(256) void gemm_kernel(const float* __restrict__ en,
                                                   const float* __restrict__ de,
                                                   const float* __restrict__ w_en,
                                                   const float* __restrict__ w_de)
{
    const int z     = blockIdx.z;
    const int b     = z >> 1;
    const int which = z & 1;

    const float* A  = which ? (de + b * NT * ND) : (en + b * NT * ND);
    const float* Bm = which ? w_de : w_en;

    const int m0 = blockIdx.y * 128;
    const int n0 = blockIdx.x * 64;

    __shared__ float As[128][36];
    __shared__ float Bs[32][68];

    const int tid  = threadIdx.x;
    const int w    = tid >> 5;
    const int lane = tid & 31;
    const int g    = lane >> 2;
    const int tig  = lane & 3;
    const int mw   = (w & 3) * 32;
    const int nw   = (w >> 2) * 32;

    float c[2][4][4];
#pragma unroll
    for (int mt = 0; mt < 2; mt++)
#pragma unroll
        for (int nt = 0; nt < 4; nt++)
#pragma unroll
            for (int i = 0; i < 4; i++) c[mt][nt][i] = 0.f;

    float4 pa[4], pb[2];
    const int ar[4] = {tid >> 3, (tid + 256) >> 3, (tid + 512) >> 3, (tid + 768) >> 3};
    const int ac    = (tid & 7) << 2;
    const int br[2] = {tid >> 4, (tid + 256) >> 4};
    const int bc    = (tid & 15) << 2;

#pragma unroll
    for (int i = 0; i < 4; i++)
        pa[i] = *(const float4*)(A + (m0 + ar[i]) * 256 + 0 + ac);
#pragma unroll
    for (int i = 0; i < 2; i++)
        pb[i] = *(const float4*)(Bm + (0 + br[i]) * 256 + n0 + bc);

    for (int t = 0; t < 8; ++t) {
        __syncthreads();
#pragma unroll
        for (int i = 0; i < 4; i++)
            *(float4*)&As[ar[i]][ac] = pa[i];
#pragma unroll
        for (int i = 0; i < 2; i++)
            *(float4*)&Bs[br[i]][bc] = pb[i];
        __syncthreads();

        if (t < 7) {
            int k0 = (t + 1) * 32;
#pragma unroll
            for (int i = 0; i < 4; i++)
                pa[i] = *(const float4*)(A + (m0 + ar[i]) * 256 + k0 + ac);
#pragma unroll
            for (int i = 0; i < 2; i++)
                pb[i] = *(const float4*)(Bm + (k0 + br[i]) * 256 + n0 + bc);
        }

#pragma unroll
        for (int kt = 0; kt < 4; kt++) {
            unsigned a[2][4];
#pragma unroll
            for (int mt = 0; mt < 2; mt++) {
                int r = mw + mt * 16 + g;
                a[mt][0] = f2tf(As[r][kt * 8 + tig]);
                a[mt][1] = f2tf(As[r + 8][kt * 8 + tig]);
                a[mt][2] = f2tf(As[r][kt * 8 + tig + 4]);
                a[mt][3] = f2tf(As[r + 8][kt * 8 + tig + 4]);
            }
#pragma unroll
            for (int nt = 0; nt < 4; nt++) {
                unsigned b0 = f2tf(Bs[kt * 8 + tig][nw + nt * 8 + g]);
                unsigned b1 = f2tf(Bs[kt * 8 + tig + 4][nw + nt * 8 + g]);
                mma_tf32(c[0][nt], a[0], b0, b1);
                mma_tf32(c[1][nt], a[1], b0, b1);
            }
        }
    }

    if (which == 0) {
        __half* dst = d_aeT_h + b * NU * NT;
#pragma unroll
        for (int mt = 0; mt < 2; mt++)
#pragma unroll
            for (int nt = 0; nt < 4; nt++) {
                int e0 = m0 + mw + mt * 16 + g;
                int u0 = n0 + nw + nt * 8 + 2 * tig;
                dst[u0 * NT + e0]           = __float2half(c[mt][nt][0]);
                dst[(u0 + 1) * NT + e0]     = __float2half(c[mt][nt][1]);
                dst[u0 * NT + e0 + 8]       = __float2half(c[mt][nt][2]);
                dst[(u0 + 1) * NT + e0 + 8] = __float2half(c[mt][nt][3]);
            }
    } else {
        float* dst = d_ad + b * NT * NU;
#pragma unroll
        for (int mt = 0; mt < 2; mt++)
#pragma unroll
            for (int nt = 0; nt < 4; nt++) {
                int row = m0 + mw + mt * 16 + g;
                int col = n0 + nw + nt * 8 + 2 * tig;
                *(float2*)(dst + row * NU + col)       = make_float2(c[mt][nt][0], c[mt][nt][1]);
                *(float2*)(dst + (row + 8) * NU + col) = make_float2(c[mt][nt][2], c[mt][nt][3]);
            }
    }
}

// ---------------------------------------------------------------------------
// Context GEMM (tf32): out[b][t][d] = de[b][t][d] + sum_e alpha[b][t][e]*en[b][e][d]
// Same tiling as front GEMM; A = alpha (row-major t x e), B = en (e x d).
// ---------------------------------------------------------------------------
__global__ __launch_bounds__(256) void ctx_kernel(const float* __restrict__ en,
                                                  const float* __restrict__ de,
                                                  float* __restrict__ out)
{
    const int b = blockIdx.z;
    const float* A  = d_alpha + b * NT * NT;
    const float* Bm = en + b * NT * ND;

    const int m0 = blockIdx.y * 128;
    const int n0 = blockIdx.x * 64;

    __shared__ float As[128][36];
    __shared__ float Bs[32][68];

    const int tid  = threadIdx.x;
    const int w    = tid >> 5;
    const int lane = tid & 31;
    const int g    = lane >> 2;
    const int tig  = lane & 3;
    const int mw   = (w & 3) * 32;
    const int nw   = (w >> 2) * 32;

    float c[2][4][4];
#pragma unroll
    for (int mt = 0; mt < 2; mt++)
#pragma unroll
        for (int nt = 0; nt < 4; nt++)
#pragma unroll
            for (int i = 0; i < 4; i++) c[mt][nt][i] = 0.f;

    float4 pa[4], pb[2];
    const int ar[4] = {tid >> 3, (tid + 256) >> 3, (tid + 512) >> 3, (tid + 768) >> 3};
    const int ac    = (tid & 7) << 2;
    const int br[2] = {tid >> 4, (tid + 256) >> 4};
    const int bc    = (tid & 15) << 2;

#pragma unroll
    for (int i = 0; i < 4; i++)
        pa[i] = *(const float4*)(A + (m0 + ar[i]) * 256 + 0 + ac);
#pragma unroll
    for (int i = 0; i < 2; i++)
        pb[i] = *(const float4*)(Bm + (0 + br[i]) * 256 + n0 + bc);

    for (int t = 0; t < 8; ++t) {
        __syncthreads();
#pragma unroll
        for (int i = 0; i < 4; i++)
            *(float4*)&As[ar[i]][ac] = pa[i];
#pragma unroll
        for (int i = 0; i < 2; i++)
            *(float4*)&Bs[br[i]][bc] = pb[i];
        __syncthreads();

        if (t < 7) {
            int k0 = (t + 1) * 32;
#pragma unroll
            for (int i = 0; i < 4; i++)
                pa[i] = *(const float4*)(A + (m0 + ar[i]) * 256 + k0 + ac);
#pragma unroll
            for (int i = 0; i < 2; i++)
                pb[i] = *(const float4*)(Bm + (k0 + br[i]) * 256 + n0 + bc);
        }

#pragma unroll
        for (int kt = 0; kt < 4; kt++) {
            unsigned a[2][4];
#pragma unroll
            for (int mt = 0; mt < 2; mt++) {
                int r = mw + mt * 16 + g;
                a[mt][0] = f2tf(As[r][kt * 8 + tig]);
                a[mt][1] = f2tf(As[r + 8][kt * 8 + tig]);
                a[mt][2] = f2tf(As[r][kt * 8 + tig + 4]);
                a[mt][3] = f2tf(As[r + 8][kt * 8 + tig + 4]);
            }
#pragma unroll
            for (int nt = 0; nt < 4; nt++) {
                unsigned b0 = f2tf(Bs[kt * 8 + tig][nw + nt * 8 + g]);
                unsigned b1 = f2tf(Bs[kt * 8 + tig + 4][nw + nt * 8 + g]);
                mma_tf32(c[0][nt], a[0], b0, b1);
                mma_tf32(c[1][nt], a[1], b0, b1);
            }
        }
    }

    // epilogue: out = de + C
    const float* deb = de + b * NT * ND;
    float* ob = out + b * NT * ND;
#pragma unroll
    for (int mt = 0; mt < 2; mt++)
#pragma unroll
        for (int nt = 0; nt < 4; nt++) {
            int row = m0 + mw + mt * 16 + g;
            int col = n0 + nw + nt * 8 + 2 * tig;
            float2 d0 = *(const float2*)(deb + row * ND + col);
            float2 d1 = *(const float2*)(deb + (row + 8) * ND + col);
            *(float2*)(ob + row * ND + col) =
                make_float2(c[mt][nt][0] + d0.x, c[mt][nt][1] + d0.y);
            *(float2*)(ob + (row + 8) * ND + col) =
                make_float2(c[mt][nt][2] + d1.x, c[mt][nt][3] + d1.y);
        }
}

// ---------------------------------------------------------------------------
// Attn kernel: scores (19 MUFU + 13 poly per 32-u tile) + softmax; stores
// alpha fp32 to d_alpha. Context phase moved to ctx_kernel (tensor pipe).
// ---------------------------------------------------------------------------
#define UT 32
#define TILE_HALFS (UT * 256)
#define NTILES (256 / UT)
#define NM 19

__device__ __forceinline__ void stage_tile(unsigned sbase, const __half* g, int tid)
{
    unsigned s = sbase + tid * 16;
    const char* gp = (const char*)g + tid * 16;
#pragma unroll
    for (int i = 0; i < 4; i++)
        asm volatile("cp.async.cg.shared.global [%0], [%1], 16;\n"
                     :: "r"(s + i * 4096), "l"(gp + i * 4096) : "memory");
    asm volatile("cp.async.commit_group;" ::: "memory");
}

struct PC { __half2 c0, c1, c2, c3, c4, c5, cl; };

__device__ __forceinline__ __half2 ptanh(__half2 x, const PC& P)
{
    __half2 xc = __hmax2(__hmin2(x, P.cl), __hneg2(P.cl));
    __half2 z  = __hmul2(xc, xc);
    __half2 h  = __hfma2(P.c5, z, P.c4);
    h = __hfma2(h, z, P.c3);
    h = __hfma2(h, z, P.c2);
    h = __hfma2(h, z, P.c1);
    h = __hfma2(h, z, P.c0);
    return __hmul2(xc, h);
}

__global__ __launch_bounds__(256) void attn_kernel(const float* __restrict__ nu)
{
    const int b   = blockIdx.x >> 6;
    const int t0  = (blockIdx.x & 63) << 2;
    const int tid = threadIdx.x;

    __shared__ __half buf[2][TILE_HALFS];
    __shared__ uint4  pk[256];
    __shared__ float  red[8];

    const unsigned sb0 = (unsigned)__cvta_generic_to_shared(&buf[0][0]);
    const unsigned sb1 = (unsigned)__cvta_generic_to_shared(&buf[1][0]);
    const unsigned sbb[2] = {sb0, sb1};

    const __half* aeg = d_aeT_h + b * NU * NT;

    PC P;
    P.c0 = __float2half2_rn(0.992381f);
    P.c1 = __float2half2_rn(-0.282962f);
    P.c2 = __float2half2_rn(0.065192f);
    P.c3 = __float2half2_rn(-0.0087342f);
    P.c4 = __float2half2_rn(0.00059761f);
    P.c5 = __float2half2_rn(-1.6085e-5f);
    P.cl = __float2half2_rn(3.398f);

    stage_tile(sb0, aeg, tid);
    {
        const float* ap = d_ad + (b * NT + t0) * NU + tid;
        __half2 ad01 = __floats2half2_rn(ap[0],      ap[NU]);
        __half2 ad23 = __floats2half2_rn(ap[2 * NU], ap[3 * NU]);
        __half2 nu2  = __float2half2_rn(nu[tid]);
        uint4 p;
        p.x = *(unsigned*)&ad01;
        p.y = *(unsigned*)&ad23;
        p.z = *(unsigned*)&nu2;
        p.w = 0;
        pk[tid] = p;
    }

    float m0 = 0.f, m1 = 0.f, m2 = 0.f, m3 = 0.f;
    for (int t = 0; t < NTILES; ++t) {
        if (t < NTILES - 1)
            stage_tile(sbb[(t + 1) & 1], aeg + (t + 1) * TILE_HALFS, tid);
        if (t < NTILES - 1)
            asm volatile("cp.async.wait_group 1;" ::: "memory");
        else
            asm volatile("cp.async.wait_group 0;" ::: "memory");
        __syncthreads();

        const __half* sa = &buf[t & 1][tid];
        const int u0 = t * UT;

        __half2 am01 = __float2half2_rn(0.f);
        __half2 am23 = __float2half2_rn(0.f);
        __half2 ap01 = __float2half2_rn(0.f);
        __half2 ap23 = __float2half2_rn(0.f);

#pragma unroll
        for (int i = 0; i < NM; i++) {
            {
                __half  a  = sa[i << 8];
                uint4   p  = pk[u0 + i];
                __half2 ah = __half2half2(a);
                __half2 c01 = __hadd2(ah, *(__half2*)&p.x);
                __half2 c23 = __hadd2(ah, *(__half2*)&p.y);
                unsigned t01, t23;
                asm("tanh.approx.f16x2 %0, %1;" : "=r"(t01) : "r"(*(unsigned*)&c01));
                asm("tanh.approx.f16x2 %0, %1;" : "=r"(t23) : "r"(*(unsigned*)&c23));
                am01 = __hfma2(*(__half2*)&t01, *(__half2*)&p.z, am01);
                am23 = __hfma2(*(__half2*)&t23, *(__half2*)&p.z, am23);
            }
            if (i < UT - NM) {
                int k = NM + i;
                __half  a  = sa[k << 8];
                uint4   p  = pk[u0 + k];
                __half2 ah = __half2half2(a);
                __half2 c01 = __hadd2(ah, *(__half2*)&p.x);
                __half2 c23 = __hadd2(ah, *(__half2*)&p.y);
                __half2 t01 = ptanh(c01, P);
                __half2 t23 = ptanh(c23, P);
                ap01 = __hfma2(t01, *(__half2*)&p.z, ap01);
                ap23 = __hfma2(t23, *(__half2*)&p.z, ap23);
            }
        }
        float2 f01 = __half22float2(am01);
        float2 f23 = __half22float2(am23);
        float2 g01 = __half22float2(ap01);
        float2 g23 = __half22float2(ap23);
        m0 += f01.x + g01.x; m1 += f01.y + g01.y;
        m2 += f23.x + g23.x; m3 += f23.y + g23.y;
        __syncthreads();
    }

    // ---- softmax over e for the 4 rows, store alpha fp32 ----
    float mu[4] = {m0, m1, m2, m3};
    float al[4];
#pragma unroll
    for (int tt = 0; tt < 4; tt++) {
        float v  = mu[tt];
        float mx = v;
#pragma unroll
        for (int o = 16; o; o >>= 1) mx = fmaxf(mx, __shfl_xor_sync(0xffffffffu, mx, o));
        if ((tid & 31) == 0) red[tid >> 5] = mx;
        __syncthreads();
        mx = fmaxf(fmaxf(fmaxf(red[0], red[1]), fmaxf(red[2], red[3])),
                   fmaxf(fmaxf(red[4], red[5]), fmaxf(red[6], red[7])));
        __syncthreads();
        float ex = __expf(v - mx);
        float s  = ex;
#pragma unroll
        for (int o = 16; o; o >>= 1) s += __shfl_xor_sync(0xffffffffu, s, o);
        if ((tid & 31) == 0) red[tid >> 5] = s;
        __syncthreads();
        s = ((red[0] + red[1]) + (red[2] + red[3])) + ((red[4] + red[5]) + (red[6] + red[7]));
        __syncthreads();
        al[tt] = __fdividef(ex, s);
    }
    float* ap = d_alpha + (b * NT + t0) * NT + tid;
#pragma unroll
    for (int tt = 0; tt < 4; tt++)
        ap[tt * NT] = al[tt];
}

extern "C" void kernel_launch(void* const* d_in, const int* in_sizes, int n_in,
                              void* d_out, int out_size)
{
    const float* en   = (const float*)d_in[0];
    const float* de   = (const float*)d_in[1];
    const float* w_en = (const float*)d_in[2];
    const float* w_de = (const float*)d_in[3];
    const float* nu   = (const float*)d_in[4];
    float* out = (float*)d_out;

    dim3 gg(4, 2, 16);
    gemm_kernel<<<gg, 256>>>(en, de, w_en, w_de);
    attn_kernel<<<NB * (NT / 4), 256>>>(nu);
    dim3 gc(4, 2, 8);
    ctx_kernel<<<gc, 256>>>(en, de, out);
}

// round 13
// speedup vs baseline: 1.6078x; 1.0225x over previous
#include <cuda_runtime.h>
#include <cuda_bf16.h>
#include <cuda_fp16.h>

#define NB 8
#define NT 256
#define ND 256
#define NU 256

__device__ __half d_aeT_h[NB * NU * NT];  // aeT[b][u][e] fp16
__device__ float  d_ad   [NB * NT * NU];  // ad [b][t][u] fp32
__device__ float  d_alpha[NB * NT * NT];  // alpha[b][t][e] fp32

// ---------------------------------------------------------------------------
// tf32 MMA helpers
// ---------------------------------------------------------------------------
__device__ __forceinline__ unsigned f2tf(float x)
{
    unsigned r;
    asm("cvt.rna.tf32.f32 %0, %1;" : "=r"(r) : "f"(x));
    return r;
}

__device__ __forceinline__ void mma_tf32(float c[4], const unsigned a[4],
                                         unsigned b0, unsigned b1)
{
    asm volatile(
        "mma.sync.aligned.m16n8k8.row.col.f32.tf32.tf32.f32 "
        "{%0,%1,%2,%3}, {%4,%5,%6,%7}, {%8,%9}, {%0,%1,%2,%3};"
        : "+f"(c[0]), "+f"(c[1]), "+f"(c[2]), "+f"(c[3])
        : "r"(a[0]), "r"(a[1]), "r"(a[2]), "r"(a[3]), "r"(b0), "r"(b1));
}

__device__ __forceinline__ uint4 tf4(float4 v)
{
    return make_uint4(f2tf(v.x), f2tf(v.y), f2tf(v.z), f2tf(v.w));
}

// ---------------------------------------------------------------------------
// Front GEMM (tf32): att_en -> d_aeT_h (fp16, transposed), att_de -> d_ad.
// tf32 conversion done ONCE at SMEM-store time; inner loop is pure LDS+MMA.
// ---------------------------------------------------------------------------
__global__ __launch_bounds__(256) void gemm_kernel(const float* __restrict__ en,
                                                   const float* __restrict__ de,
                                                   const float* __restrict__ w_en,
                                                   const float* __restrict__ w_de)
{
    const int z     = blockIdx.z;
    const int b     = z >> 1;
    const int which = z & 1;

    const float* A  = which ? (de + b * NT * ND) : (en + b * NT * ND);
    const float* Bm = which ? w_de : w_en;

    const int m0 = blockIdx.y * 128;
    const int n0 = blockIdx.x * 64;

    __shared__ unsigned As[128][36];   // tf32 bits
    __shared__ unsigned Bs[32][68];    // tf32 bits

    const int tid  = threadIdx.x;
    const int w    = tid >> 5;
    const int lane = tid & 31;
    const int g    = lane >> 2;
    const int tig  = lane & 3;
    const int mw   = (w & 3) * 32;
    const int nw   = (w >> 2) * 32;

    float c[2][4][4];
#pragma unroll
    for (int mt = 0; mt < 2; mt++)
#pragma unroll
        for (int nt = 0; nt < 4; nt++)
#pragma unroll
            for (int i = 0; i < 4; i++) c[mt][nt][i] = 0.f;

    float4 pa[4], pb[2];
    const int ar[4] = {tid >> 3, (tid + 256) >> 3, (tid + 512) >> 3, (tid + 768) >> 3};
    const int ac    = (tid & 7) << 2;
    const int br[2] = {tid >> 4, (tid + 256) >> 4};
    const int bc    = (tid & 15) << 2;

#pragma unroll
    for (int i = 0; i < 4; i++)
        pa[i] = *(const float4*)(A + (m0 + ar[i]) * 256 + 0 + ac);
#pragma unroll
    for (int i = 0; i < 2; i++)
        pb[i] = *(const float4*)(Bm + (0 + br[i]) * 256 + n0 + bc);

    for (int t = 0; t < 8; ++t) {
        __syncthreads();
#pragma unroll
        for (int i = 0; i < 4; i++)
            *(uint4*)&As[ar[i]][ac] = tf4(pa[i]);
#pragma unroll
        for (int i = 0; i < 2; i++)
            *(uint4*)&Bs[br[i]][bc] = tf4(pb[i]);
        __syncthreads();

        if (t < 7) {
            int k0 = (t + 1) * 32;
#pragma unroll
            for (int i = 0; i < 4; i++)
                pa[i] = *(const float4*)(A + (m0 + ar[i]) * 256 + k0 + ac);
#pragma unroll
            for (int i = 0; i < 2; i++)
                pb[i] = *(const float4*)(Bm + (k0 + br[i]) * 256 + n0 + bc);
        }

#pragma unroll
        for (int kt = 0; kt < 4; kt++) {
            unsigned a[2][4];
#pragma unroll
            for (int mt = 0; mt < 2; mt++) {
                int r = mw + mt * 16 + g;
                a[mt][0] = As[r][kt * 8 + tig];
                a[mt][1] = As[r + 8][kt * 8 + tig];
                a[mt][2] = As[r][kt * 8 + tig + 4];
                a[mt][3] = As[r + 8][kt * 8 + tig + 4];
            }
#pragma unroll
            for (int nt = 0; nt < 4; nt++) {
                unsigned b0 = Bs[kt * 8 + tig][nw + nt * 8 + g];
                unsigned b1 = Bs[kt * 8 + tig + 4][nw + nt * 8 + g];
                mma_tf32(c[0][nt], a[0], b0, b1);
                mma_tf32(c[1][nt], a[1], b0, b1);
            }
        }
    }

    if (which == 0) {
        __half* dst = d_aeT_h + b * NU * NT;
#pragma unroll
        for (int mt = 0; mt < 2; mt++)
#pragma unroll
            for (int nt = 0; nt < 4; nt++) {
                int e0 = m0 + mw + mt * 16 + g;
                int u0 = n0 + nw + nt * 8 + 2 * tig;
                dst[u0 * NT + e0]           = __float2half(c[mt][nt][0]);
                dst[(u0 + 1) * NT + e0]     = __float2half(c[mt][nt][1]);
                dst[u0 * NT + e0 + 8]       = __float2half(c[mt][nt][2]);
                dst[(u0 + 1) * NT + e0 + 8] = __float2half(c[mt][nt][3]);
            }
    } else {
        float* dst = d_ad + b * NT * NU;
#pragma unroll
        for (int mt = 0; mt < 2; mt++)
#pragma unroll
            for (int nt = 0; nt < 4; nt++) {
                int row = m0 + mw + mt * 16 + g;
                int col = n0 + nw + nt * 8 + 2 * tig;
                *(float2*)(dst + row * NU + col)       = make_float2(c[mt][nt][0], c[mt][nt][1]);
                *(float2*)(dst + (row + 8) * NU + col) = make_float2(c[mt][nt][2], c[mt][nt][3]);
            }
    }
}

// ---------------------------------------------------------------------------
// Context GEMM (tf32): out = de + alpha @ en. Same store-time cvt.
// ---------------------------------------------------------------------------
__global__ __launch_bounds__(256) void ctx_kernel(const float* __restrict__ en,
                                                  const float* __restrict__ de,
                                                  float* __restrict__ out)
{
    const int b = blockIdx.z;
    const float* A  = d_alpha + b * NT * NT;
    const float* Bm = en + b * NT * ND;

    const int m0 = blockIdx.y * 128;
    const int n0 = blockIdx.x * 64;

    __shared__ unsigned As[128][36];
    __shared__ unsigned Bs[32][68];

    const int tid  = threadIdx.x;
    const int w    = tid >> 5;
    const int lane = tid & 31;
    const int g    = lane >> 2;
    const int tig  = lane & 3;
    const int mw   = (w & 3) * 32;
    const int nw   = (w >> 2) * 32;

    float c[2][4][4];
#pragma unroll
    for (int mt = 0; mt < 2; mt++)
#pragma unroll
        for (int nt = 0; nt < 4; nt++)
#pragma unroll
            for (int i = 0; i < 4; i++) c[mt][nt][i] = 0.f;

    float4 pa[4], pb[2];
    const int ar[4] = {tid >> 3, (tid + 256) >> 3, (tid + 512) >> 3, (tid + 768) >> 3};
    const int ac    = (tid & 7) << 2;
    const int br[2] = {tid >> 4, (tid + 256) >> 4};
    const int bc    = (tid & 15) << 2;

#pragma unroll
    for (int i = 0; i < 4; i++)
        pa[i] = *(const float4*)(A + (m0 + ar[i]) * 256 + 0 + ac);
#pragma unroll
    for (int i = 0; i < 2; i++)
        pb[i] = *(const float4*)(Bm + (0 + br[i]) * 256 + n0 + bc);

    for (int t = 0; t < 8; ++t) {
        __syncthreads();
#pragma unroll
        for (int i = 0; i < 4; i++)
            *(uint4*)&As[ar[i]][ac] = tf4(pa[i]);
#pragma unroll
        for (int i = 0; i < 2; i++)
            *(uint4*)&Bs[br[i]][bc] = tf4(pb[i]);
        __syncthreads();

        if (t < 7) {
            int k0 = (t + 1) * 32;
#pragma unroll
            for (int i = 0; i < 4; i++)
                pa[i] = *(const float4*)(A + (m0 + ar[i]) * 256 + k0 + ac);
#pragma unroll
            for (int i = 0; i < 2; i++)
                pb[i] = *(const float4*)(Bm + (k0 + br[i]) * 256 + n0 + bc);
        }

#pragma unroll
        for (int kt = 0; kt < 4; kt++) {
            unsigned a[2][4];
#pragma unroll
            for (int mt = 0; mt < 2; mt++) {
                int r = mw + mt * 16 + g;
                a[mt][0] = As[r][kt * 8 + tig];
                a[mt][1] = As[r + 8][kt * 8 + tig];
                a[mt][2] = As[r][kt * 8 + tig + 4];
                a[mt][3] = As[r + 8][kt * 8 + tig + 4];
            }
#pragma unroll
            for (int nt = 0; nt < 4; nt++) {
                unsigned b0 = Bs[kt * 8 + tig][nw + nt * 8 + g];
                unsigned b1 = Bs[kt * 8 + tig + 4][nw + nt * 8 + g];
                mma_tf32(c[0][nt], a[0], b0, b1);
                mma_tf32(c[1][nt], a[1], b0, b1);
            }
        }
    }

    const float* deb = de + b * NT * ND;
    float* ob = out + b * NT * ND;
#pragma unroll
    for (int mt = 0; mt < 2; mt++)
#pragma unroll
        for (int nt = 0; nt < 4; nt++) {
            int row = m0 + mw + mt * 16 + g;
            int col = n0 + nw + nt * 8 + 2 * tig;
            float2 d0 = *(const float2*)(deb + row * ND + col);
            float2 d1 = *(const float2*)(deb + (row + 8) * ND + col);
            *(float2*)(ob + row * ND + col) =
                make_float2(c[mt][nt][0] + d0.x, c[mt][nt][1] + d0.y);
            *(float2*)(ob + (row + 8) * ND + col) =
                make_float2(c[mt][nt][2] + d1.x, c[mt][nt][3] + d1.y);
        }
}

// ---------------------------------------------------------------------------
// Attn kernel: scores (19 MUFU + 13 poly per 32-u tile) + batched softmax;
// stores alpha fp32. Context handled by ctx_kernel (tensor pipe).
// ---------------------------------------------------------------------------
#define UT 32
#define TILE_HALFS (UT * 256)
#define NTILES (256 / UT)
#define NM 19

__device__ __forceinline__ void stage_tile(unsigned sbase, const __half* g, int tid)
{
    unsigned s = sbase + tid * 16;
    const char* gp = (const char*)g + tid * 16;
#pragma unroll
    for (int i = 0; i < 4; i++)
        asm volatile("cp.async.cg.shared.global [%0], [%1], 16;\n"
                     :: "r"(s + i * 4096), "l"(gp + i * 4096) : "memory");
    asm volatile("cp.async.commit_group;" ::: "memory");
}

struct PC { __half2 c0, c1, c2, c3, c4, c5, cl; };

__device__ __forceinline__ __half2 ptanh(__half2 x, const PC& P)
{
    __half2 xc = __hmax2(__hmin2(x, P.cl), __hneg2(P.cl));
    __half2 z  = __hmul2(xc, xc);
    __half2 h  = __hfma2(P.c5, z, P.c4);
    h = __hfma2(h, z, P.c3);
    h = __hfma2(h, z, P.c2);
    h = __hfma2(h, z, P.c1);
    h = __hfma2(h, z, P.c0);
    return __hmul2(xc, h);
}

__global__ __launch_bounds__(256) void attn_kernel(const float* __restrict__ nu)
{
    const int b   = blockIdx.x >> 6;
    const int t0  = (blockIdx.x & 63) << 2;
    const int tid = threadIdx.x;
    const int wid = tid >> 5;

    __shared__ __half buf[2][TILE_HALFS];
    __shared__ uint4  pk[256];
    __shared__ float4 redM[8];
    __shared__ float4 redS[8];

    const unsigned sb0 = (unsigned)__cvta_generic_to_shared(&buf[0][0]);
    const unsigned sb1 = (unsigned)__cvta_generic_to_shared(&buf[1][0]);
    const unsigned sbb[2] = {sb0, sb1};

    const __half* aeg = d_aeT_h + b * NU * NT;

    PC P;
    P.c0 = __float2half2_rn(0.992381f);
    P.c1 = __float2half2_rn(-0.282962f);
    P.c2 = __float2half2_rn(0.065192f);
    P.c3 = __float2half2_rn(-0.0087342f);
    P.c4 = __float2half2_rn(0.00059761f);
    P.c5 = __float2half2_rn(-1.6085e-5f);
    P.cl = __float2half2_rn(3.398f);

    stage_tile(sb0, aeg, tid);
    {
        const float* ap = d_ad + (b * NT + t0) * NU + tid;
        __half2 ad01 = __floats2half2_rn(ap[0],      ap[NU]);
        __half2 ad23 = __floats2half2_rn(ap[2 * NU], ap[3 * NU]);
        __half2 nu2  = __float2half2_rn(nu[tid]);
        uint4 p;
        p.x = *(unsigned*)&ad01;
        p.y = *(unsigned*)&ad23;
        p.z = *(unsigned*)&nu2;
        p.w = 0;
        pk[tid] = p;
    }

    float m0 = 0.f, m1 = 0.f, m2 = 0.f, m3 = 0.f;
    for (int t = 0; t < NTILES; ++t) {
        if (t < NTILES - 1)
            stage_tile(sbb[(t + 1) & 1], aeg + (t + 1) * TILE_HALFS, tid);
        if (t < NTILES - 1)
            asm volatile("cp.async.wait_group 1;" ::: "memory");
        else
            asm volatile("cp.async.wait_group 0;" ::: "memory");
        __syncthreads();

        const __half* sa = &buf[t & 1][tid];
        const int u0 = t * UT;

        __half2 am01 = __float2half2_rn(0.f);
        __half2 am23 = __float2half2_rn(0.f);
        __half2 ap01 = __float2half2_rn(0.f);
        __half2 ap23 = __float2half2_rn(0.f);

#pragma unroll
        for (int i = 0; i < NM; i++) {
            {
                __half  a  = sa[i << 8];
                uint4   p  = pk[u0 + i];
                __half2 ah = __half2half2(a);
                __half2 c01 = __hadd2(ah, *(__half2*)&p.x);
                __half2 c23 = __hadd2(ah, *(__half2*)&p.y);
                unsigned t01, t23;
                asm("tanh.approx.f16x2 %0, %1;" : "=r"(t01) : "r"(*(unsigned*)&c01));
                asm("tanh.approx.f16x2 %0, %1;" : "=r"(t23) : "r"(*(unsigned*)&c23));
                am01 = __hfma2(*(__half2*)&t01, *(__half2*)&p.z, am01);
                am23 = __hfma2(*(__half2*)&t23, *(__half2*)&p.z, am23);
            }
            if (i < UT - NM) {
                int k = NM + i;
                __half  a  = sa[k << 8];
                uint4   p  = pk[u0 + k];
                __half2 ah = __half2half2(a);
                __half2 c01 = __hadd2(ah, *(__half2*)&p.x);
                __half2 c23 = __hadd2(ah, *(__half2*)&p.y);
                __half2 t01 = ptanh(c01, P);
                __half2 t23 = ptanh(c23, P);
                ap01 = __hfma2(t01, *(__half2*)&p.z, ap01);
                ap23 = __hfma2(t23, *(__half2*)&p.z, ap23);
            }
        }
        float2 f01 = __half22float2(am01);
        float2 f23 = __half22float2(am23);
        float2 g01 = __half22float2(ap01);
        float2 g23 = __half22float2(ap23);
        m0 += f01.x + g01.x; m1 += f01.y + g01.y;
        m2 += f23.x + g23.x; m3 += f23.y + g23.y;
        __syncthreads();
    }

    // ---- batched softmax over e (all 4 rows, 2 barriers) ----
    float4 mu = make_float4(m0, m1, m2, m3);
    float4 mx = mu;
#pragma unroll
    for (int o = 16; o; o >>= 1) {
        mx.x = fmaxf(mx.x, __shfl_xor_sync(0xffffffffu, mx.x, o));
        mx.y = fmaxf(mx.y, __shfl_xor_sync(0xffffffffu, mx.y, o));
        mx.z = fmaxf(mx.z, __shfl_xor_sync(0xffffffffu, mx.z, o));
        mx.w = fmaxf(mx.w, __shfl_xor_sync(0xffffffffu, mx.w, o));
    }
    if ((tid & 31) == 0) redM[wid] = mx;
    __syncthreads();
    mx = redM[0];
#pragma unroll
    for (int i = 1; i < 8; i++) {
        float4 r = redM[i];
        mx.x = fmaxf(mx.x, r.x); mx.y = fmaxf(mx.y, r.y);
        mx.z = fmaxf(mx.z, r.z); mx.w = fmaxf(mx.w, r.w);
    }
    float4 ex = make_float4(__expf(mu.x - mx.x), __expf(mu.y - mx.y),
                            __expf(mu.z - mx.z), __expf(mu.w - mx.w));
    float4 s = ex;
#pragma unroll
    for (int o = 16; o; o >>= 1) {
        s.x += __shfl_xor_sync(0xffffffffu, s.x, o);
        s.y += __shfl_xor_sync(0xffffffffu, s.y, o);
        s.z += __shfl_xor_sync(0xffffffffu, s.z, o);
        s.w += __shfl_xor_sync(0xffffffffu, s.w, o);
    }
    if ((tid & 31) == 0) redS[wid] = s;
    __syncthreads();
    s = redS[0];
#pragma unroll
    for (int i = 1; i < 8; i++) {
        float4 r = redS[i];
        s.x += r.x; s.y += r.y; s.z += r.z; s.w += r.w;
    }

    float* ap = d_alpha + (b * NT + t0) * NT + tid;
    ap[0]      = __fdividef(ex.x, s.x);
    ap[NT]     = __fdividef(ex.y, s.y);
    ap[2 * NT] = __fdividef(ex.z, s.z);
    ap[3 * NT] = __fdividef(ex.w, s.w);
}

extern "C" void kernel_launch(void* const* d_in, const int* in_sizes, int n_in,
                              void* d_out, int out_size)
{
    const float* en   = (const float*)d_in[0];
    const float* de   = (const float*)d_in[1];
    const float* w_en = (const float*)d_in[2];
    const float* w_de = (const float*)d_in[3];
    const float* nu   = (const float*)d_in[4];
    float* out = (float*)d_out;

    dim3 gg(4, 2, 16);
    gemm_kernel<<<gg, 256>>>(en, de, w_en, w_de);
    attn_kernel<<<NB * (NT / 4), 256>>>(nu);
    dim3 gc(4, 2, 8);
    ctx_kernel<<<gc, 256>>>(en, de, out);
}